// round 15
// baseline (speedup 1.0000x reference)
#include <cuda_runtime.h>
#include <cuda_bf16.h>
#include <cuda_fp16.h>
#include <math.h>
#include <stdint.h>

#define T_SEQ 2048
#define C_DIM 256
#define H_NUM 16
#define NOPE 32
#define ROPE 64
#define HD 96
#define VD 32
#define KEEP 512
#define WIN 128
#define BMAX 2
#define EPSF 1e-6f

// ---------------- device scratch ----------------
__device__ float g_costab[T_SEQ * 32];
__device__ float g_sintab[T_SEQ * 32];
__device__ float g_cq[BMAX * T_SEQ * 96];
__device__ __nv_bfloat16 g_cqh[BMAX * T_SEQ * 96];
__device__ __nv_bfloat16 g_cql[BMAX * T_SEQ * 96];
__device__ float g_ckv[BMAX * T_SEQ * 32];
__device__ float g_kr[BMAX * T_SEQ * 64];
__device__ float g_imp[BMAX * T_SEQ];
__device__ int   g_idx[BMAX * KEEP];
__device__ float g_xpart[BMAX * 16 * C_DIM];
__device__ float g_gate[BMAX * 3];
__device__ float g_q [BMAX * H_NUM * T_SEQ * HD];
__device__ __nv_bfloat16 g_k1hi[BMAX * H_NUM * T_SEQ * HD];
__device__ __nv_bfloat16 g_k1lo[BMAX * H_NUM * T_SEQ * HD];
__device__ __nv_bfloat16 g_kshi[BMAX * H_NUM * KEEP * HD];
__device__ __nv_bfloat16 g_kslo[BMAX * H_NUM * KEEP * HD];
__device__ __nv_bfloat16 g_kwhi[BMAX * H_NUM * T_SEQ * HD];
__device__ __nv_bfloat16 g_kwlo[BMAX * H_NUM * T_SEQ * HD];
// V stored packed as half2 (low = even row, high = odd row), pair-row major
__device__ uint32_t g_v1p[BMAX * H_NUM * (T_SEQ / 2) * VD];
__device__ uint32_t g_vsp[BMAX * H_NUM * (KEEP / 2) * VD];
__device__ uint32_t g_vwp[BMAX * H_NUM * (T_SEQ / 2) * VD];
__device__ float g_O0[BMAX * T_SEQ * H_NUM * VD];
__device__ float g_O1[BMAX * T_SEQ * H_NUM * VD];
__device__ float g_O2[BMAX * T_SEQ * H_NUM * VD];
// bf16 hi/lo copies for tensor-core projections
__device__ __nv_bfloat16 g_xh[BMAX * T_SEQ * C_DIM];
__device__ __nv_bfloat16 g_xl[BMAX * T_SEQ * C_DIM];
__device__ __nv_bfloat16 g_wwk_h[C_DIM * 1536], g_wwk_l[C_DIM * 1536];
__device__ __nv_bfloat16 g_wsk_h[C_DIM * 1536], g_wsk_l[C_DIM * 1536];
__device__ __nv_bfloat16 g_wwv_h[C_DIM * 512],  g_wwv_l[C_DIM * 512];
__device__ __nv_bfloat16 g_wsv_h[C_DIM * 512],  g_wsv_l[C_DIM * 512];
__device__ __nv_bfloat16 g_wq_h[96 * 1536],     g_wq_l[96 * 1536];

__device__ __forceinline__ void mma16bf(float* c, const uint32_t* a, uint32_t b0, uint32_t b1) {
    asm volatile("mma.sync.aligned.m16n8k16.row.col.f32.bf16.bf16.f32 "
        "{%0,%1,%2,%3}, {%4,%5,%6,%7}, {%8,%9}, {%0,%1,%2,%3};"
        : "+f"(c[0]), "+f"(c[1]), "+f"(c[2]), "+f"(c[3])
        : "r"(a[0]), "r"(a[1]), "r"(a[2]), "r"(a[3]), "r"(b0), "r"(b1));
}
__device__ __forceinline__ void mma16h(float* c, const uint32_t* a, uint32_t b0, uint32_t b1) {
    asm volatile("mma.sync.aligned.m16n8k16.row.col.f32.f16.f16.f32 "
        "{%0,%1,%2,%3}, {%4,%5,%6,%7}, {%8,%9}, {%0,%1,%2,%3};"
        : "+f"(c[0]), "+f"(c[1]), "+f"(c[2]), "+f"(c[3])
        : "r"(a[0]), "r"(a[1]), "r"(a[2]), "r"(a[3]), "r"(b0), "r"(b1));
}
__device__ __forceinline__ void ldsm4(uint32_t& r0, uint32_t& r1, uint32_t& r2, uint32_t& r3,
                                      uint32_t addr) {
    asm volatile("ldmatrix.sync.aligned.m8n8.x4.shared.b16 {%0,%1,%2,%3}, [%4];"
        : "=r"(r0), "=r"(r1), "=r"(r2), "=r"(r3) : "r"(addr));
}
__device__ __forceinline__ void ldsm4t(uint32_t& r0, uint32_t& r1, uint32_t& r2, uint32_t& r3,
                                       uint32_t addr) {
    asm volatile("ldmatrix.sync.aligned.m8n8.x4.trans.shared.b16 {%0,%1,%2,%3}, [%4];"
        : "=r"(r0), "=r"(r1), "=r"(r2), "=r"(r3) : "r"(addr));
}
__device__ __forceinline__ void cp16(uint32_t dst, const void* src) {
    asm volatile("cp.async.cg.shared.global [%0], [%1], 16;" :: "r"(dst), "l"(src));
}
__device__ __forceinline__ void split_store(float v, __nv_bfloat16* hi, __nv_bfloat16* lo) {
    __nv_bfloat16 h = __float2bfloat16(v);
    *hi = h;
    *lo = __float2bfloat16(v - __bfloat162float(h));
}

// ---------------- prep: rope table + colmean partials ----------------
__global__ void prep_kernel(const float* __restrict__ x, int B) {
    if ((int)blockIdx.x < 256) {
        int id = blockIdx.x * 256 + threadIdx.x;
        int t = id >> 5, i = id & 31;
        float f = (float)pow(10000.0, -(double)i / 32.0);
        float ang = (float)t * f;
        g_costab[id] = cosf(ang);
        g_sintab[id] = sinf(ang);
    } else {
        int blk = blockIdx.x - 256;
        int b = blk >> 4, chunk = blk & 15;
        int c = threadIdx.x;
        const float* xp = x + ((size_t)b * T_SEQ + chunk * 128) * C_DIM + c;
        float s = 0.f;
        #pragma unroll 4
        for (int t = 0; t < 128; ++t) s += xp[(size_t)t * C_DIM];
        g_xpart[blk * C_DIM + c] = s;
    }
}

// ---------------- bf16 hi/lo conversion of x, sel/win weights, combined Wq ----------------
__global__ void convert_kernel(const float* __restrict__ x,
                               const float* __restrict__ wwk, const float* __restrict__ wsk,
                               const float* __restrict__ wwv, const float* __restrict__ wsv,
                               const float* __restrict__ wqn, const float* __restrict__ wqr,
                               int B) {
    int seg = blockIdx.y;
    if (seg == 5) {
        for (int i = blockIdx.x * 256 + threadIdx.x; i < 96 * 1536; i += 512 * 256) {
            int c = i / 1536, col = i % 1536;
            int h = col / 96, d = col % 96;
            float v = (d < 32) ? wqn[c * 512 + h * 32 + d] : wqr[c * 1024 + h * 64 + (d - 32)];
            split_store(v, &g_wq_h[i], &g_wq_l[i]);
        }
        return;
    }
    const float* src; __nv_bfloat16 *dh, *dl; int n;
    switch (seg) {
        case 0: src = x;   dh = g_xh;    dl = g_xl;    n = B * T_SEQ * C_DIM; break;
        case 1: src = wwk; dh = g_wwk_h; dl = g_wwk_l; n = C_DIM * 1536; break;
        case 2: src = wsk; dh = g_wsk_h; dl = g_wsk_l; n = C_DIM * 1536; break;
        case 3: src = wwv; dh = g_wwv_h; dl = g_wwv_l; n = C_DIM * 512;  break;
        default: src = wsv; dh = g_wsv_h; dl = g_wsv_l; n = C_DIM * 512;  break;
    }
    for (int i = blockIdx.x * 256 + threadIdx.x; i < n; i += 512 * 256)
        split_store(src[i], &dh[i], &dl[i]);
}

// ---------------- row features + gate (gate = last block) ----------------
__global__ void row_feat_gate_kernel(const float* __restrict__ x,
                                const float* __restrict__ Wcq, const float* __restrict__ qnw,
                                const float* __restrict__ Wckv, const float* __restrict__ kvnw,
                                const float* __restrict__ Wkr, const float* __restrict__ Wimp,
                                const float* __restrict__ Wgate, int B) {
    int tid = threadIdx.x; // 256
    int lane = tid & 31, w = tid >> 5;
    if ((int)blockIdx.x == B * T_SEQ) {
        __shared__ float lg[6];
        if (w < B * 3) {
            int b = w / 3, j = w % 3;
            float s = 0.f;
            for (int c = lane; c < C_DIM; c += 32) {
                float m = 0.f;
                #pragma unroll
                for (int p = 0; p < 16; ++p) m += g_xpart[(b * 16 + p) * C_DIM + c];
                s += (m / (float)T_SEQ) * Wgate[c * 3 + j];
            }
            #pragma unroll
            for (int o = 16; o > 0; o >>= 1) s += __shfl_xor_sync(0xffffffffu, s, o);
            if (lane == 0) lg[w] = s;
        }
        __syncthreads();
        if (tid < B) {
            float a = lg[tid * 3], b2 = lg[tid * 3 + 1], c2 = lg[tid * 3 + 2];
            float mx = fmaxf(a, fmaxf(b2, c2));
            float ea = expf(a - mx), eb = expf(b2 - mx), ec = expf(c2 - mx);
            float s = ea + eb + ec;
            g_gate[tid * 3 + 0] = ea / s;
            g_gate[tid * 3 + 1] = eb / s;
            g_gate[tid * 3 + 2] = ec / s;
        }
        return;
    }
    int row = blockIdx.x;
    int t = row % T_SEQ;
    __shared__ float xs[C_DIM];
    __shared__ float krbuf[64];
    __shared__ float red[4];
    xs[tid] = x[(size_t)row * C_DIM + tid];
    __syncthreads();
    float a = 0.f;
    if (tid < 96) {
        for (int c = 0; c < C_DIM; c += 4) {
            float4 xv = *(const float4*)&xs[c];
            a += xv.x * Wcq[c * 96 + tid] + xv.y * Wcq[(c + 1) * 96 + tid]
               + xv.z * Wcq[(c + 2) * 96 + tid] + xv.w * Wcq[(c + 3) * 96 + tid];
        }
    } else if (tid < 128) {
        int j = tid - 96;
        for (int c = 0; c < C_DIM; c += 4) {
            float4 xv = *(const float4*)&xs[c];
            a += xv.x * Wckv[c * 32 + j] + xv.y * Wckv[(c + 1) * 32 + j]
               + xv.z * Wckv[(c + 2) * 32 + j] + xv.w * Wckv[(c + 3) * 32 + j];
        }
    } else if (tid < 192) {
        int j = tid - 128;
        for (int c = 0; c < C_DIM; c += 4) {
            float4 xv = *(const float4*)&xs[c];
            a += xv.x * Wkr[c * 64 + j] + xv.y * Wkr[(c + 1) * 64 + j]
               + xv.z * Wkr[(c + 2) * 64 + j] + xv.w * Wkr[(c + 3) * 64 + j];
        }
        a *= (1.f / (float)H_NUM);
        krbuf[j] = a;
    } else if (tid == 192) {
        for (int c = 0; c < C_DIM; ++c) a += xs[c] * Wimp[c];
        g_imp[row] = a;
    }
    if (w < 4) {
        float sq = a * a;
        #pragma unroll
        for (int o = 16; o > 0; o >>= 1) sq += __shfl_xor_sync(0xffffffffu, sq, o);
        if (lane == 0) red[w] = sq;
    }
    __syncthreads();
    if (tid < 96) {
        float rms_cq = rsqrtf((red[0] + red[1] + red[2]) / 96.f + EPSF);
        float v = a * rms_cq * qnw[tid];
        g_cq[(size_t)row * 96 + tid] = v;
        split_store(v, &g_cqh[(size_t)row * 96 + tid], &g_cql[(size_t)row * 96 + tid]);
    } else if (tid < 128) {
        float rms_kv = rsqrtf(red[3] / 32.f + EPSF);
        g_ckv[(size_t)row * 32 + (tid - 96)] = a * rms_kv * kvnw[tid - 96];
    } else if (tid < 160) {
        int i = tid - 128;
        float xr = krbuf[i], xi = krbuf[32 + i];
        float co = g_costab[t * 32 + i], si = g_sintab[t * 32 + i];
        g_kr[(size_t)row * 64 + i]      = xr * co - xi * si;
        g_kr[(size_t)row * 64 + 32 + i] = xr * si + xi * co;
    }
}

// ---------------- tensor-core q projection (M=64, N=96 per head, K=96) ----------------
#define QX_B 80
#define QW_B 208
__global__ void __launch_bounds__(128) qproj_tc() {
    __shared__ __align__(16) __nv_bfloat16 sxh[64 * 40], sxl[64 * 40];
    __shared__ __align__(16) __nv_bfloat16 swh[32 * 104], swl[32 * 104];
    int tid = threadIdx.x, lane = tid & 31, wr = tid >> 5;
    int g = lane >> 2, tg = lane & 3;
    int row0 = blockIdx.x * 64;
    int bq = row0 / T_SEQ, t0 = row0 % T_SEQ;
    int h = blockIdx.y;
    int wn0 = h * 96;

    uint32_t sxh_u = (uint32_t)__cvta_generic_to_shared(sxh);
    uint32_t sxl_u = (uint32_t)__cvta_generic_to_shared(sxl);
    uint32_t swh_u = (uint32_t)__cvta_generic_to_shared(swh);
    uint32_t swl_u = (uint32_t)__cvta_generic_to_shared(swl);

    float acc[12][4];
    #pragma unroll
    for (int nt = 0; nt < 12; ++nt)
        #pragma unroll
        for (int e = 0; e < 4; ++e) acc[nt][e] = 0.f;

    for (int kc = 0; kc < 3; ++kc) {
        for (int i = tid; i < 256; i += 128) {
            int r = i >> 2, c = i & 3;
            size_t src = (size_t)(row0 + r) * 96 + kc * 32 + c * 8;
            cp16(sxh_u + r * QX_B + c * 16, g_cqh + src);
            cp16(sxl_u + r * QX_B + c * 16, g_cql + src);
        }
        for (int i = tid; i < 32 * 12; i += 128) {
            int r = i / 12, c = i % 12;
            size_t src = (size_t)(kc * 32 + r) * 1536 + wn0 + c * 8;
            cp16(swh_u + r * QW_B + c * 16, g_wq_h + src);
            cp16(swl_u + r * QW_B + c * 16, g_wq_l + src);
        }
        asm volatile("cp.async.commit_group;");
        asm volatile("cp.async.wait_group 0;");
        __syncthreads();
        #pragma unroll
        for (int kt = 0; kt < 2; ++kt) {
            uint32_t aH[4], aL[4];
            uint32_t addrA = sxh_u + (wr * 16 + (lane & 15)) * QX_B + (lane >> 4) * 16 + kt * 32;
            ldsm4(aH[0], aH[1], aH[2], aH[3], addrA);
            ldsm4(aL[0], aL[1], aL[2], aL[3], addrA + (sxl_u - sxh_u));
            uint32_t addrB0 = swh_u + (kt * 16 + (lane & 15)) * QW_B + (lane >> 4) * 16;
            #pragma unroll
            for (int p = 0; p < 6; ++p) {
                uint32_t bh0, bh1, bh2, bh3, bl0, bl1, bl2, bl3;
                ldsm4t(bh0, bh1, bh2, bh3, addrB0 + p * 32);
                ldsm4t(bl0, bl1, bl2, bl3, addrB0 + p * 32 + (swl_u - swh_u));
                mma16bf(acc[2 * p],     aH, bh0, bh1);
                mma16bf(acc[2 * p],     aH, bl0, bl1);
                mma16bf(acc[2 * p],     aL, bh0, bh1);
                mma16bf(acc[2 * p + 1], aH, bh2, bh3);
                mma16bf(acc[2 * p + 1], aH, bl2, bl3);
                mma16bf(acc[2 * p + 1], aL, bh2, bh3);
            }
        }
        __syncthreads();
    }

    #pragma unroll
    for (int nt = 0; nt < 4; ++nt) {
        #pragma unroll
        for (int e = 0; e < 4; ++e) {
            int d = nt * 8 + 2 * tg + (e & 1);
            int t = t0 + wr * 16 + g + ((e & 2) ? 8 : 0);
            g_q[((size_t)(bq * H_NUM + h) * T_SEQ + t) * HD + d] = acc[nt][e];
        }
    }
    #pragma unroll
    for (int nt = 4; nt < 8; ++nt) {
        #pragma unroll
        for (int e = 0; e < 4; ++e) {
            int i = (nt - 4) * 8 + 2 * tg + (e & 1);
            int t = t0 + wr * 16 + g + ((e & 2) ? 8 : 0);
            float ar = acc[nt][e], ai = acc[nt + 4][e];
            float co = g_costab[t * 32 + i], si = g_sintab[t * 32 + i];
            size_t base = ((size_t)(bq * H_NUM + h) * T_SEQ + t) * HD;
            g_q[base + 32 + i] = ar * co - ai * si;
            g_q[base + 64 + i] = ar * si + ai * co;
        }
    }
}

// ---------------- k/v scalar pass (K=32) + topk ----------------
#define QKV_RT 16
__global__ void qkv_topk_kernel(const float* __restrict__ Wkn, const float* __restrict__ Wv,
                                int nqkv) {
    __shared__ __align__(16) char smbuf[16640];
    int tid = threadIdx.x; // 256
    if ((int)blockIdx.x >= nqkv) {
        float* v = (float*)smbuf;
        int* ix = (int*)(smbuf + 8192);
        int b = blockIdx.x - nqkv;
        for (int i = tid; i < T_SEQ; i += 256) { v[i] = g_imp[b * T_SEQ + i]; ix[i] = i; }
        __syncthreads();
        for (int k = 2; k <= T_SEQ; k <<= 1)
            for (int j = k >> 1; j > 0; j >>= 1) {
                for (int i = tid; i < T_SEQ; i += 256) {
                    int p = i ^ j;
                    if (p > i) {
                        bool up = ((i & k) == 0);
                        bool sw = up ? (v[i] < v[p]) : (v[i] > v[p]);
                        if (sw) {
                            float tv = v[i]; v[i] = v[p]; v[p] = tv;
                            int ti = ix[i]; ix[i] = ix[p]; ix[p] = ti;
                        }
                    }
                }
                __syncthreads();
            }
        for (int k = 2; k <= KEEP; k <<= 1)
            for (int j = k >> 1; j > 0; j >>= 1) {
                for (int i = tid; i < KEEP; i += 256) {
                    int p = i ^ j;
                    if (p > i) {
                        bool up = ((i & k) == 0);
                        bool sw = up ? (ix[i] > ix[p]) : (ix[i] < ix[p]);
                        if (sw) { int ti = ix[i]; ix[i] = ix[p]; ix[p] = ti; }
                    }
                }
                __syncthreads();
            }
        for (int i = tid; i < KEEP; i += 256) g_idx[b * KEEP + i] = ix[i];
        return;
    }
    const int RT = QKV_RT;
    int row0 = blockIdx.x * RT;
    int bq = row0 / T_SEQ, t0 = row0 % T_SEQ;
    float* ckvs = (float*)smbuf;
    float* krs  = ckvs + RT * 32;
    for (int i = tid; i < RT * 32; i += 256) ckvs[i] = g_ckv[(size_t)(row0 + i / 32) * 32 + (i % 32)];
    for (int i = tid; i < RT * 64; i += 256) krs[i] = g_kr[(size_t)(row0 + i / 64) * 64 + (i % 64)];
    __syncthreads();
    for (int o = tid; o < 512; o += 256) {
        int h = o >> 5, d = o & 31;
        float acc[RT], accv[RT];
        #pragma unroll
        for (int r = 0; r < RT; ++r) { acc[r] = 0.f; accv[r] = 0.f; }
        for (int c = 0; c < 32; c += 4) {
            float k0 = Wkn[c * 512 + o], k1 = Wkn[(c + 1) * 512 + o];
            float k2 = Wkn[(c + 2) * 512 + o], k3 = Wkn[(c + 3) * 512 + o];
            float v0 = Wv[c * 512 + o], v1 = Wv[(c + 1) * 512 + o];
            float v2 = Wv[(c + 2) * 512 + o], v3 = Wv[(c + 3) * 512 + o];
            #pragma unroll
            for (int r = 0; r < RT; ++r) {
                float4 q = *(const float4*)&ckvs[r * 32 + c];
                acc[r]  += q.x * k0 + q.y * k1 + q.z * k2 + q.w * k3;
                accv[r] += q.x * v0 + q.y * v1 + q.z * v2 + q.w * v3;
            }
        }
        #pragma unroll
        for (int r = 0; r < RT; ++r) {
            size_t o2 = ((size_t)(bq * H_NUM + h) * T_SEQ + t0 + r) * HD + d;
            split_store(acc[r], &g_k1hi[o2], &g_k1lo[o2]);
        }
        #pragma unroll
        for (int r = 0; r < RT; r += 2) {
            __half2 hp = __floats2half2_rn(accv[r], accv[r + 1]);
            g_v1p[((size_t)(bq * H_NUM + h) * (T_SEQ / 2) + (t0 + r) / 2) * VD + d] = *(uint32_t*)&hp;
        }
    }
    for (int i = tid; i < RT * H_NUM * 64; i += 256) {
        int r = i / (H_NUM * 64); int rem = i % (H_NUM * 64); int h = rem / 64; int d = rem % 64;
        size_t o2 = ((size_t)(bq * H_NUM + h) * T_SEQ + t0 + r) * HD + 32 + d;
        split_store(krs[r * 64 + d], &g_k1hi[o2], &g_k1lo[o2]);
    }
}

// ---------------- tensor-core sel+window K,V projection ----------------
#define XROW_B 144
#define WROW_B 208
template <bool ISV>
__global__ void __launch_bounds__(128) kvproj_tc(int nwin) {
    __shared__ __align__(16) __nv_bfloat16 sxh[64 * 72], sxl[64 * 72];
    __shared__ __align__(16) __nv_bfloat16 swh[64 * 104], swl[64 * 104];
    __shared__ int sidx[64];
    const int NTN = ISV ? 8 : 12;
    int tid = threadIdx.x, lane = tid & 31, wr = tid >> 5;
    int g = lane >> 2, tg = lane & 3;
    bool sel = (int)blockIdx.x >= nwin;
    int rb = sel ? (blockIdx.x - nwin) : blockIdx.x;
    const int Tk = sel ? KEEP : T_SEQ;
    int row0 = rb * 64;
    int bq = row0 / Tk, s0 = row0 % Tk;
    int wn0 = blockIdx.y * (ISV ? 64 : 96);
    const int WN = ISV ? 512 : 1536;
    const __nv_bfloat16* Wh = ISV ? (sel ? g_wsv_h : g_wwv_h) : (sel ? g_wsk_h : g_wwk_h);
    const __nv_bfloat16* Wl = ISV ? (sel ? g_wsv_l : g_wwv_l) : (sel ? g_wsk_l : g_wwk_l);

    if (tid < 64) sidx[tid] = sel ? g_idx[bq * KEEP + s0 + tid] : (s0 + tid);
    __syncthreads();

    uint32_t sxh_u = (uint32_t)__cvta_generic_to_shared(sxh);
    uint32_t sxl_u = (uint32_t)__cvta_generic_to_shared(sxl);
    uint32_t swh_u = (uint32_t)__cvta_generic_to_shared(swh);
    uint32_t swl_u = (uint32_t)__cvta_generic_to_shared(swl);

    float acc[12][4];
    #pragma unroll
    for (int nt = 0; nt < 12; ++nt)
        #pragma unroll
        for (int e = 0; e < 4; ++e) acc[nt][e] = 0.f;

    const int nch = NTN;
    for (int kc = 0; kc < 4; ++kc) {
        for (int i = tid; i < 512; i += 128) {
            int r = i >> 3, c = i & 7;
            size_t src = (size_t)(bq * T_SEQ + sidx[r]) * C_DIM + kc * 64 + c * 8;
            cp16(sxh_u + r * XROW_B + c * 16, g_xh + src);
            cp16(sxl_u + r * XROW_B + c * 16, g_xl + src);
        }
        for (int i = tid; i < 64 * nch; i += 128) {
            int r = i / nch, c = i % nch;
            size_t src = (size_t)(kc * 64 + r) * WN + wn0 + c * 8;
            cp16(swh_u + r * WROW_B + c * 16, Wh + src);
            cp16(swl_u + r * WROW_B + c * 16, Wl + src);
        }
        asm volatile("cp.async.commit_group;");
        asm volatile("cp.async.wait_group 0;");
        __syncthreads();
        #pragma unroll
        for (int kt = 0; kt < 4; ++kt) {
            uint32_t aH[4], aL[4];
            uint32_t addrA = sxh_u + (wr * 16 + (lane & 15)) * XROW_B + (lane >> 4) * 16 + kt * 32;
            ldsm4(aH[0], aH[1], aH[2], aH[3], addrA);
            ldsm4(aL[0], aL[1], aL[2], aL[3], addrA + (sxl_u - sxh_u));
            uint32_t addrB0 = swh_u + (kt * 16 + (lane & 15)) * WROW_B + (lane >> 4) * 16;
            #pragma unroll
            for (int p = 0; p < NTN / 2; ++p) {
                uint32_t bh0, bh1, bh2, bh3, bl0, bl1, bl2, bl3;
                ldsm4t(bh0, bh1, bh2, bh3, addrB0 + p * 32);
                ldsm4t(bl0, bl1, bl2, bl3, addrB0 + p * 32 + (swl_u - swh_u));
                mma16bf(acc[2 * p],     aH, bh0, bh1);
                mma16bf(acc[2 * p],     aH, bl0, bl1);
                mma16bf(acc[2 * p],     aL, bh0, bh1);
                mma16bf(acc[2 * p + 1], aH, bh2, bh3);
                mma16bf(acc[2 * p + 1], aH, bl2, bl3);
                mma16bf(acc[2 * p + 1], aL, bh2, bh3);
            }
        }
        __syncthreads();
    }

    if (!ISV) {
        __nv_bfloat16* Khi = sel ? g_kshi : g_kwhi;
        __nv_bfloat16* Klo = sel ? g_kslo : g_kwlo;
        int h = blockIdx.y;
        #pragma unroll
        for (int nt = 0; nt < 4; ++nt) {
            #pragma unroll
            for (int e = 0; e < 4; ++e) {
                int d = nt * 8 + 2 * tg + (e & 1);
                int s = s0 + wr * 16 + g + ((e & 2) ? 8 : 0);
                size_t o2 = ((size_t)(bq * H_NUM + h) * Tk + s) * HD + d;
                split_store(acc[nt][e], &Khi[o2], &Klo[o2]);
            }
        }
        #pragma unroll
        for (int nt = 4; nt < 8; ++nt) {
            #pragma unroll
            for (int e = 0; e < 4; ++e) {
                int i = (nt - 4) * 8 + 2 * tg + (e & 1);
                int s = s0 + wr * 16 + g + ((e & 2) ? 8 : 0);
                float ar = acc[nt][e], ai = acc[nt + 4][e];
                float co = g_costab[s * 32 + i], si = g_sintab[s * 32 + i];
                size_t base = ((size_t)(bq * H_NUM + h) * Tk + s) * HD;
                split_store(ar * co - ai * si, &Khi[base + 32 + i], &Klo[base + 32 + i]);
                split_store(ar * si + ai * co, &Khi[base + 64 + i], &Klo[base + 64 + i]);
            }
        }
    } else {
        uint32_t* Vp = sel ? g_vsp : g_vwp;
        #pragma unroll
        for (int nt = 0; nt < 8; ++nt) {
            #pragma unroll
            for (int e = 0; e < 4; ++e) {
                float v0 = acc[nt][e];
                float v1 = __shfl_down_sync(0xffffffffu, v0, 4);
                if (!(g & 1)) {
                    int gc = wn0 + nt * 8 + 2 * tg + (e & 1);
                    int h = gc >> 5, d = gc & 31;
                    int s = s0 + wr * 16 + g + ((e & 2) ? 8 : 0);
                    __half2 hp = __floats2half2_rn(v0, v1);
                    Vp[((size_t)(bq * H_NUM + h) * (Tk / 2) + (s >> 1)) * VD + d] = *(uint32_t*)&hp;
                }
            }
        }
    }
}

// ---------------- fused flash attention (AQB=128, 256 threads, 8 warps) ----------------
#define AQB 128
#define AKB 64
#define KROW_B   208
#define KBUF_B   (AKB * KROW_B)
#define LDVP 44
#define VBUF_B   (32 * LDVP * 4)
#define BUF_STRIDE (2 * KBUF_B + VBUF_B)
#define FA_SMEM (2 * BUF_STRIDE)

__global__ void __launch_bounds__(256) attn_all() {
    extern __shared__ char smc[];
    uint32_t smem_u = (uint32_t)__cvta_generic_to_shared(smc);

    // grid.x = 48: mode0 tiles 0..15 (reversed), mode1 16..31, mode2 32..47
    int bx = blockIdx.x;
    int mode, qt;
    if (bx < 16)      { mode = 0; qt = 15 - bx; }
    else if (bx < 32) { mode = 1; qt = bx - 16; }
    else              { mode = 2; qt = bx - 32; }
    int qt0 = qt * AQB;
    const int Tk = (mode == 1) ? KEEP : T_SEQ;
    int b = blockIdx.z, h = blockIdx.y;
    int tid = threadIdx.x;
    int w = tid >> 5, lane = tid & 31;
    int g = lane >> 2, tg = lane & 3;
    int r0 = w * 16;
    int R0 = qt0 + r0;   // warp's first q row

    const __nv_bfloat16* KHI = (mode == 1) ? g_kshi : (mode == 2) ? g_kwhi : g_k1hi;
    const __nv_bfloat16* KLO = (mode == 1) ? g_kslo : (mode == 2) ? g_kwlo : g_k1lo;
    const uint32_t* VP = (mode == 1) ? g_vsp : (mode == 2) ? g_vwp : g_v1p;
    float* Oout = (mode == 1) ? g_O1 : (mode == 2) ? g_O2 : g_O0;
    const __nv_bfloat16* KbaseH = KHI + (size_t)(b * H_NUM + h) * Tk * HD;
    const __nv_bfloat16* KbaseL = KLO + (size_t)(b * H_NUM + h) * Tk * HD;
    const uint32_t* VPbase = VP + (size_t)(b * H_NUM + h) * (Tk / 2) * VD;
    const float* Qbase = g_q + ((size_t)(b * H_NUM + h) * T_SEQ + qt0) * HD;
    const float qscale = 0.14724444f; // log2(e)/sqrt(96)

    uint32_t lmoff = (uint32_t)(lane & 7) * KROW_B + (uint32_t)(lane >> 3) * 16;

    for (int i = tid; i < 2 * 32 * 8; i += 256) {
        int buf = i >> 8, rem = i & 255;
        int pr = rem >> 3, c = 32 + (rem & 7);
        ((uint32_t*)(smc + buf * BUF_STRIDE + 2 * KBUF_B))[pr * LDVP + c] =
            (c == 32) ? 0x3C003C00u : 0u;
    }
    __syncthreads();

    uint32_t qhi[6][4], qlo[6][4];
    #pragma unroll
    for (int kc = 0; kc < 6; ++kc) {
        #pragma unroll
        for (int e = 0; e < 4; ++e) {
            int row = r0 + g + (e & 1) * 8;
            int col = kc * 16 + 2 * tg + (e & 2) * 4;
            float2 qv = *(const float2*)(Qbase + (size_t)row * HD + col);
            qv.x *= qscale; qv.y *= qscale;
            __nv_bfloat16 hx = __float2bfloat16(qv.x);
            __nv_bfloat16 hy = __float2bfloat16(qv.y);
            qhi[kc][e] = ((uint32_t)__bfloat16_as_ushort(hy) << 16) | __bfloat16_as_ushort(hx);
            __nv_bfloat16 lx = __float2bfloat16(qv.x - __bfloat162float(hx));
            __nv_bfloat16 ly = __float2bfloat16(qv.y - __bfloat162float(hy));
            qlo[kc][e] = ((uint32_t)__bfloat16_as_ushort(ly) << 16) | __bfloat16_as_ushort(lx);
        }
    }

    float oacc[5][4];
    #pragma unroll
    for (int nt = 0; nt < 5; ++nt)
        #pragma unroll
        for (int e = 0; e < 4; ++e) oacc[nt][e] = 0.f;

    int kend = (mode == 1) ? KEEP : (qt0 + AQB);
    int k0 = 0;
    if (mode == 2) { int a0 = qt0 - (WIN - 1); k0 = (a0 > 0) ? (a0 & ~(AKB - 1)) : 0; }

    auto prefetch = [&](int kt, int buf) {
        uint32_t kd = smem_u + buf * BUF_STRIDE;
        const uint4* sH = (const uint4*)(KbaseH + (size_t)kt * HD);
        const uint4* sL = (const uint4*)(KbaseL + (size_t)kt * HD);
        #pragma unroll
        for (int it = 0; it < 3; ++it) {
            int i = tid + it * 256;
            int r = i / 12, c = i % 12;
            cp16(kd + r * KROW_B + c * 16, sH + i);
            cp16(kd + KBUF_B + r * KROW_B + c * 16, sL + i);
        }
        {
            int pc = tid;
            cp16(kd + 2 * KBUF_B + (pc >> 3) * (LDVP * 4) + (pc & 7) * 16,
                 (const uint4*)(VPbase + (size_t)(kt / 2) * VD) + pc);
        }
    };

    prefetch(k0, 0);
    asm volatile("cp.async.commit_group;");
    int buf = 0;

    for (int kt = k0; kt < kend; kt += AKB) {
        int nxt = kt + AKB;
        if (nxt < kend) {
            prefetch(nxt, buf ^ 1);
            asm volatile("cp.async.commit_group;");
            asm volatile("cp.async.wait_group 1;");
        } else {
            asm volatile("cp.async.wait_group 0;");
        }
        __syncthreads();

        // warp-level skip of fully-masked tiles (contributes exactly 0)
        bool active = true;
        if (mode == 0) active = (kt <= R0 + 15);
        else if (mode == 2) active = (kt <= R0 + 15) && (kt + AKB - 1 >= R0 - (WIN - 1));

        if (active) {
            uint32_t baseH = smem_u + buf * BUF_STRIDE + lmoff;
            uint32_t baseL = baseH + KBUF_B;
            const uint32_t* Vpb = (const uint32_t*)(smc + buf * BUF_STRIDE + 2 * KBUF_B);

            float sacc[8][4];
            #pragma unroll
            for (int nt = 0; nt < 8; ++nt)
                #pragma unroll
                for (int e = 0; e < 4; ++e) sacc[nt][e] = 0.f;
            #pragma unroll
            for (int nt = 0; nt < 8; ++nt) {
                uint32_t aH = baseH + (uint32_t)nt * (8 * KROW_B);
                uint32_t aL = baseL + (uint32_t)nt * (8 * KROW_B);
                #pragma unroll
                for (int kp = 0; kp < 3; ++kp) {
                    uint32_t h0, h1, h2, h3, l0, l1, l2, l3;
                    ldsm4(h0, h1, h2, h3, aH + kp * 64);
                    ldsm4(l0, l1, l2, l3, aL + kp * 64);
                    int kc = 2 * kp;
                    mma16bf(sacc[nt], qhi[kc], h0, h1);
                    mma16bf(sacc[nt], qhi[kc], l0, l1);
                    mma16bf(sacc[nt], qlo[kc], h0, h1);
                    mma16bf(sacc[nt], qhi[kc + 1], h2, h3);
                    mma16bf(sacc[nt], qhi[kc + 1], l2, l3);
                    mma16bf(sacc[nt], qlo[kc + 1], h2, h3);
                }
            }

            bool need_mask = (mode == 2) || (mode == 0 && kt + AKB > R0);
            if (need_mask) {
                #pragma unroll
                for (int nt = 0; nt < 8; ++nt) {
                    #pragma unroll
                    for (int e = 0; e < 4; ++e) {
                        int key = kt + nt * 8 + 2 * tg + (e & 1);
                        int row = R0 + g + ((e & 2) ? 8 : 0);
                        bool ok = key <= row;
                        if (mode == 2) ok = ok && (row - key < WIN);
                        if (!ok) sacc[nt][e] = -1e30f;
                    }
                }
            }

            uint32_t ph2[8][2];
            #pragma unroll
            for (int nt = 0; nt < 8; ++nt) {
                __half2 e0 = h2exp2(__floats2half2_rn(sacc[nt][0], sacc[nt][1]));
                __half2 e1 = h2exp2(__floats2half2_rn(sacc[nt][2], sacc[nt][3]));
                ph2[nt][0] = *(uint32_t*)&e0;
                ph2[nt][1] = *(uint32_t*)&e1;
            }

            #pragma unroll
            for (int kc2 = 0; kc2 < 4; ++kc2) {
                uint32_t pa[4] = { ph2[2 * kc2][0], ph2[2 * kc2][1],
                                   ph2[2 * kc2 + 1][0], ph2[2 * kc2 + 1][1] };
                #pragma unroll
                for (int nt2 = 0; nt2 < 5; ++nt2) {
                    uint32_t b0 = Vpb[(kc2 * 8 + tg) * LDVP + nt2 * 8 + g];
                    uint32_t b1 = Vpb[(kc2 * 8 + tg + 4) * LDVP + nt2 * 8 + g];
                    mma16h(oacc[nt2], pa, b0, b1);
                }
            }
        }
        __syncthreads();
        buf ^= 1;
    }

    float l0 = __shfl_sync(0xffffffffu, oacc[4][0], lane & 28);
    float l1 = __shfl_sync(0xffffffffu, oacc[4][2], lane & 28);
    float gte = g_gate[b * 3 + mode];
    float inv0 = gte / l0, inv1 = gte / l1;
    #pragma unroll
    for (int nt = 0; nt < 4; ++nt) {
        #pragma unroll
        for (int e = 0; e < 4; ++e) {
            int row = R0 + g + ((e & 2) ? 8 : 0);
            int col = nt * 8 + 2 * tg + (e & 1);
            Oout[((size_t)(b * T_SEQ + row) * H_NUM + h) * VD + col] =
                oacc[nt][e] * ((e & 2) ? inv1 : inv0);
        }
    }
}

// ---------------- final projection (sums 3 branch buffers) ----------------
__global__ void proj_kernel(const float* __restrict__ Wproj, float* __restrict__ out) {
    const int RT = 16;
    int row0 = blockIdx.x * RT;
    int tid = threadIdx.x; // 256
    __shared__ float Os[RT][512];
    const float4* O0 = (const float4*)(g_O0 + ((size_t)row0 << 9));
    const float4* O1 = (const float4*)(g_O1 + ((size_t)row0 << 9));
    const float4* O2 = (const float4*)(g_O2 + ((size_t)row0 << 9));
    for (int i = tid; i < RT * 128; i += 256) {
        float4 a = O0[i], b = O1[i], c = O2[i];
        a.x += b.x + c.x; a.y += b.y + c.y; a.z += b.z + c.z; a.w += b.w + c.w;
        ((float4*)Os)[i] = a;
    }
    __syncthreads();
    float acc[RT];
    #pragma unroll
    for (int r = 0; r < RT; ++r) acc[r] = 0.f;
    for (int c = 0; c < 512; c += 4) {
        float w0 = Wproj[c * 256 + tid], w1 = Wproj[(c + 1) * 256 + tid];
        float w2 = Wproj[(c + 2) * 256 + tid], w3 = Wproj[(c + 3) * 256 + tid];
        #pragma unroll
        for (int r = 0; r < RT; ++r) {
            float4 o = *(const float4*)&Os[r][c];
            acc[r] += o.x * w0 + o.y * w1 + o.z * w2 + o.w * w3;
        }
    }
    #pragma unroll
    for (int r = 0; r < RT; ++r) out[(size_t)(row0 + r) * 256 + tid] = acc[r];
}

// ---------------- launch ----------------
extern "C" void kernel_launch(void* const* d_in, const int* in_sizes, int n_in,
                              void* d_out, int out_size) {
    const float* x     = (const float*)d_in[0];
    const float* Wcq   = (const float*)d_in[1];
    const float* qnw   = (const float*)d_in[2];
    const float* Wqn   = (const float*)d_in[3];
    const float* Wqr   = (const float*)d_in[4];
    const float* Wckv  = (const float*)d_in[5];
    const float* kvnw  = (const float*)d_in[6];
    const float* Wkn   = (const float*)d_in[7];
    const float* Wv    = (const float*)d_in[8];
    const float* Wkr   = (const float*)d_in[9];
    const float* Wimp  = (const float*)d_in[10];
    const float* Wselk = (const float*)d_in[11];
    const float* Wselv = (const float*)d_in[12];
    const float* Wwink = (const float*)d_in[13];
    const float* Wwinv = (const float*)d_in[14];
    const float* Wgate = (const float*)d_in[15];
    const float* Wproj = (const float*)d_in[16];
    float* out = (float*)d_out;
    int B = in_sizes[0] / (T_SEQ * C_DIM);
    if (B < 1) B = 1; if (B > BMAX) B = BMAX;

    cudaFuncSetAttribute(attn_all, cudaFuncAttributeMaxDynamicSharedMemorySize, FA_SMEM);

    prep_kernel<<<256 + B * 16, 256>>>(x, B);
    convert_kernel<<<dim3(512, 6), 256>>>(x, Wwink, Wselk, Wwinv, Wselv, Wqn, Wqr, B);
    row_feat_gate_kernel<<<B * T_SEQ + 1, 256>>>(x, Wcq, qnw, Wckv, kvnw, Wkr, Wimp, Wgate, B);

    qproj_tc<<<dim3(B * T_SEQ / 64, 16), 128>>>();
    int nqkv = B * T_SEQ / QKV_RT;
    qkv_topk_kernel<<<nqkv + B, 256>>>(Wkn, Wv, nqkv);

    int nwin64 = B * T_SEQ / 64, nsel64 = B * KEEP / 64;
    kvproj_tc<false><<<dim3(nwin64 + nsel64, 16), 128>>>(nwin64);
    kvproj_tc<true ><<<dim3(nwin64 + nsel64, 8), 128>>>(nwin64);

    dim3 agrid(48, H_NUM, B);
    attn_all<<<agrid, 256, FA_SMEM>>>();

    proj_kernel<<<B * T_SEQ / 16, 256>>>(Wproj, out);
}

// round 16
// speedup vs baseline: 1.0481x; 1.0481x over previous
#include <cuda_runtime.h>
#include <cuda_bf16.h>
#include <cuda_fp16.h>
#include <math.h>
#include <stdint.h>

#define T_SEQ 2048
#define C_DIM 256
#define H_NUM 16
#define NOPE 32
#define ROPE 64
#define HD 96
#define VD 32
#define KEEP 512
#define WIN 128
#define BMAX 2
#define EPSF 1e-6f

// ---------------- device scratch ----------------
__device__ float g_costab[T_SEQ * 32];
__device__ float g_sintab[T_SEQ * 32];
__device__ float g_cq[BMAX * T_SEQ * 96];
__device__ float g_ckv[BMAX * T_SEQ * 32];
__device__ float g_kr[BMAX * T_SEQ * 64];
__device__ float g_imp[BMAX * T_SEQ];
__device__ int   g_idx[BMAX * KEEP];
__device__ float g_xpart[BMAX * 16 * C_DIM];
__device__ float g_gate[BMAX * 3];
__device__ float g_q [BMAX * H_NUM * T_SEQ * HD];
__device__ __nv_bfloat16 g_k1hi[BMAX * H_NUM * T_SEQ * HD];
__device__ __nv_bfloat16 g_k1lo[BMAX * H_NUM * T_SEQ * HD];
__device__ __nv_bfloat16 g_kshi[BMAX * H_NUM * KEEP * HD];
__device__ __nv_bfloat16 g_kslo[BMAX * H_NUM * KEEP * HD];
__device__ __nv_bfloat16 g_kwhi[BMAX * H_NUM * T_SEQ * HD];
__device__ __nv_bfloat16 g_kwlo[BMAX * H_NUM * T_SEQ * HD];
// V stored packed as half2 (low = even row, high = odd row), pair-row major
__device__ uint32_t g_v1p[BMAX * H_NUM * (T_SEQ / 2) * VD];
__device__ uint32_t g_vsp[BMAX * H_NUM * (KEEP / 2) * VD];
__device__ uint32_t g_vwp[BMAX * H_NUM * (T_SEQ / 2) * VD];
__device__ float g_O0[BMAX * T_SEQ * H_NUM * VD];
__device__ float g_O1[BMAX * T_SEQ * H_NUM * VD];
__device__ float g_O2[BMAX * T_SEQ * H_NUM * VD];
// bf16 hi/lo copies for tensor-core kvproj
__device__ __nv_bfloat16 g_xh[BMAX * T_SEQ * C_DIM];
__device__ __nv_bfloat16 g_xl[BMAX * T_SEQ * C_DIM];
__device__ __nv_bfloat16 g_wwk_h[C_DIM * 1536], g_wwk_l[C_DIM * 1536];
__device__ __nv_bfloat16 g_wsk_h[C_DIM * 1536], g_wsk_l[C_DIM * 1536];
__device__ __nv_bfloat16 g_wwv_h[C_DIM * 512],  g_wwv_l[C_DIM * 512];
__device__ __nv_bfloat16 g_wsv_h[C_DIM * 512],  g_wsv_l[C_DIM * 512];

__device__ __forceinline__ void mma16bf(float* c, const uint32_t* a, uint32_t b0, uint32_t b1) {
    asm volatile("mma.sync.aligned.m16n8k16.row.col.f32.bf16.bf16.f32 "
        "{%0,%1,%2,%3}, {%4,%5,%6,%7}, {%8,%9}, {%0,%1,%2,%3};"
        : "+f"(c[0]), "+f"(c[1]), "+f"(c[2]), "+f"(c[3])
        : "r"(a[0]), "r"(a[1]), "r"(a[2]), "r"(a[3]), "r"(b0), "r"(b1));
}
__device__ __forceinline__ void mma16h(float* c, const uint32_t* a, uint32_t b0, uint32_t b1) {
    asm volatile("mma.sync.aligned.m16n8k16.row.col.f32.f16.f16.f32 "
        "{%0,%1,%2,%3}, {%4,%5,%6,%7}, {%8,%9}, {%0,%1,%2,%3};"
        : "+f"(c[0]), "+f"(c[1]), "+f"(c[2]), "+f"(c[3])
        : "r"(a[0]), "r"(a[1]), "r"(a[2]), "r"(a[3]), "r"(b0), "r"(b1));
}
__device__ __forceinline__ void ldsm4(uint32_t& r0, uint32_t& r1, uint32_t& r2, uint32_t& r3,
                                      uint32_t addr) {
    asm volatile("ldmatrix.sync.aligned.m8n8.x4.shared.b16 {%0,%1,%2,%3}, [%4];"
        : "=r"(r0), "=r"(r1), "=r"(r2), "=r"(r3) : "r"(addr));
}
__device__ __forceinline__ void ldsm4t(uint32_t& r0, uint32_t& r1, uint32_t& r2, uint32_t& r3,
                                       uint32_t addr) {
    asm volatile("ldmatrix.sync.aligned.m8n8.x4.trans.shared.b16 {%0,%1,%2,%3}, [%4];"
        : "=r"(r0), "=r"(r1), "=r"(r2), "=r"(r3) : "r"(addr));
}
__device__ __forceinline__ void cp16(uint32_t dst, const void* src) {
    asm volatile("cp.async.cg.shared.global [%0], [%1], 16;" :: "r"(dst), "l"(src));
}
__device__ __forceinline__ void split_store(float v, __nv_bfloat16* hi, __nv_bfloat16* lo) {
    __nv_bfloat16 h = __float2bfloat16(v);
    *hi = h;
    *lo = __float2bfloat16(v - __bfloat162float(h));
}

// ---------------- prep: rope table + colmean partials ----------------
__global__ void prep_kernel(const float* __restrict__ x, int B) {
    if ((int)blockIdx.x < 256) {
        int id = blockIdx.x * 256 + threadIdx.x;
        int t = id >> 5, i = id & 31;
        float f = (float)pow(10000.0, -(double)i / 32.0);
        float ang = (float)t * f;
        g_costab[id] = cosf(ang);
        g_sintab[id] = sinf(ang);
    } else {
        int blk = blockIdx.x - 256;
        int b = blk >> 4, chunk = blk & 15;
        int c = threadIdx.x;
        const float* xp = x + ((size_t)b * T_SEQ + chunk * 128) * C_DIM + c;
        float s = 0.f;
        #pragma unroll 4
        for (int t = 0; t < 128; ++t) s += xp[(size_t)t * C_DIM];
        g_xpart[blk * C_DIM + c] = s;
    }
}

// ---------------- bf16 hi/lo conversion of x and sel/win weights ----------------
__global__ void convert_kernel(const float* __restrict__ x,
                               const float* __restrict__ wwk, const float* __restrict__ wsk,
                               const float* __restrict__ wwv, const float* __restrict__ wsv,
                               int B) {
    int seg = blockIdx.y;
    const float* src; __nv_bfloat16 *dh, *dl; int n;
    switch (seg) {
        case 0: src = x;   dh = g_xh;    dl = g_xl;    n = B * T_SEQ * C_DIM; break;
        case 1: src = wwk; dh = g_wwk_h; dl = g_wwk_l; n = C_DIM * 1536; break;
        case 2: src = wsk; dh = g_wsk_h; dl = g_wsk_l; n = C_DIM * 1536; break;
        case 3: src = wwv; dh = g_wwv_h; dl = g_wwv_l; n = C_DIM * 512;  break;
        default: src = wsv; dh = g_wsv_h; dl = g_wsv_l; n = C_DIM * 512;  break;
    }
    for (int i = blockIdx.x * 256 + threadIdx.x; i < n; i += 512 * 256)
        split_store(src[i], &dh[i], &dl[i]);
}

// ---------------- row features + gate (gate = last block) ----------------
__global__ void row_feat_gate_kernel(const float* __restrict__ x,
                                const float* __restrict__ Wcq, const float* __restrict__ qnw,
                                const float* __restrict__ Wckv, const float* __restrict__ kvnw,
                                const float* __restrict__ Wkr, const float* __restrict__ Wimp,
                                const float* __restrict__ Wgate, int B) {
    int tid = threadIdx.x; // 256
    int lane = tid & 31, w = tid >> 5;
    if ((int)blockIdx.x == B * T_SEQ) {
        __shared__ float lg[6];
        if (w < B * 3) {
            int b = w / 3, j = w % 3;
            float s = 0.f;
            for (int c = lane; c < C_DIM; c += 32) {
                float m = 0.f;
                #pragma unroll
                for (int p = 0; p < 16; ++p) m += g_xpart[(b * 16 + p) * C_DIM + c];
                s += (m / (float)T_SEQ) * Wgate[c * 3 + j];
            }
            #pragma unroll
            for (int o = 16; o > 0; o >>= 1) s += __shfl_xor_sync(0xffffffffu, s, o);
            if (lane == 0) lg[w] = s;
        }
        __syncthreads();
        if (tid < B) {
            float a = lg[tid * 3], b2 = lg[tid * 3 + 1], c2 = lg[tid * 3 + 2];
            float mx = fmaxf(a, fmaxf(b2, c2));
            float ea = expf(a - mx), eb = expf(b2 - mx), ec = expf(c2 - mx);
            float s = ea + eb + ec;
            g_gate[tid * 3 + 0] = ea / s;
            g_gate[tid * 3 + 1] = eb / s;
            g_gate[tid * 3 + 2] = ec / s;
        }
        return;
    }
    int row = blockIdx.x;
    int t = row % T_SEQ;
    __shared__ float xs[C_DIM];
    __shared__ float krbuf[64];
    __shared__ float red[4];
    xs[tid] = x[(size_t)row * C_DIM + tid];
    __syncthreads();
    float a = 0.f;
    if (tid < 96) {
        for (int c = 0; c < C_DIM; c += 4) {
            float4 xv = *(const float4*)&xs[c];
            a += xv.x * Wcq[c * 96 + tid] + xv.y * Wcq[(c + 1) * 96 + tid]
               + xv.z * Wcq[(c + 2) * 96 + tid] + xv.w * Wcq[(c + 3) * 96 + tid];
        }
    } else if (tid < 128) {
        int j = tid - 96;
        for (int c = 0; c < C_DIM; c += 4) {
            float4 xv = *(const float4*)&xs[c];
            a += xv.x * Wckv[c * 32 + j] + xv.y * Wckv[(c + 1) * 32 + j]
               + xv.z * Wckv[(c + 2) * 32 + j] + xv.w * Wckv[(c + 3) * 32 + j];
        }
    } else if (tid < 192) {
        int j = tid - 128;
        for (int c = 0; c < C_DIM; c += 4) {
            float4 xv = *(const float4*)&xs[c];
            a += xv.x * Wkr[c * 64 + j] + xv.y * Wkr[(c + 1) * 64 + j]
               + xv.z * Wkr[(c + 2) * 64 + j] + xv.w * Wkr[(c + 3) * 64 + j];
        }
        a *= (1.f / (float)H_NUM);
        krbuf[j] = a;
    } else if (tid == 192) {
        for (int c = 0; c < C_DIM; ++c) a += xs[c] * Wimp[c];
        g_imp[row] = a;
    }
    if (w < 4) {
        float sq = a * a;
        #pragma unroll
        for (int o = 16; o > 0; o >>= 1) sq += __shfl_xor_sync(0xffffffffu, sq, o);
        if (lane == 0) red[w] = sq;
    }
    __syncthreads();
    if (tid < 96) {
        float rms_cq = rsqrtf((red[0] + red[1] + red[2]) / 96.f + EPSF);
        g_cq[(size_t)row * 96 + tid] = a * rms_cq * qnw[tid];
    } else if (tid < 128) {
        float rms_kv = rsqrtf(red[3] / 32.f + EPSF);
        g_ckv[(size_t)row * 32 + (tid - 96)] = a * rms_kv * kvnw[tid - 96];
    } else if (tid < 160) {
        int i = tid - 128;
        float xr = krbuf[i], xi = krbuf[32 + i];
        float co = g_costab[t * 32 + i], si = g_sintab[t * 32 + i];
        g_kr[(size_t)row * 64 + i]      = xr * co - xi * si;
        g_kr[(size_t)row * 64 + 32 + i] = xr * si + xi * co;
    }
}

// ---------------- qkv (RT=16, pass-split via blockIdx.y) + topk ----------------
#define QKV_RT 16
__global__ void qkv_topk_kernel(const float* __restrict__ Wqn, const float* __restrict__ Wqr,
                                const float* __restrict__ Wkn, const float* __restrict__ Wv,
                                int nqkv) {
    __shared__ __align__(16) char smbuf[16640];
    int tid = threadIdx.x; // 256
    int pass = blockIdx.y;
    if ((int)blockIdx.x >= nqkv) {
        if (pass != 0) return;
        float* v = (float*)smbuf;
        int* ix = (int*)(smbuf + 8192);
        int b = blockIdx.x - nqkv;
        for (int i = tid; i < T_SEQ; i += 256) { v[i] = g_imp[b * T_SEQ + i]; ix[i] = i; }
        __syncthreads();
        for (int k = 2; k <= T_SEQ; k <<= 1)
            for (int j = k >> 1; j > 0; j >>= 1) {
                for (int i = tid; i < T_SEQ; i += 256) {
                    int p = i ^ j;
                    if (p > i) {
                        bool up = ((i & k) == 0);
                        bool sw = up ? (v[i] < v[p]) : (v[i] > v[p]);
                        if (sw) {
                            float tv = v[i]; v[i] = v[p]; v[p] = tv;
                            int ti = ix[i]; ix[i] = ix[p]; ix[p] = ti;
                        }
                    }
                }
                __syncthreads();
            }
        for (int k = 2; k <= KEEP; k <<= 1)
            for (int j = k >> 1; j > 0; j >>= 1) {
                for (int i = tid; i < KEEP; i += 256) {
                    int p = i ^ j;
                    if (p > i) {
                        bool up = ((i & k) == 0);
                        bool sw = up ? (ix[i] > ix[p]) : (ix[i] < ix[p]);
                        if (sw) { int ti = ix[i]; ix[i] = ix[p]; ix[p] = ti; }
                    }
                }
                __syncthreads();
            }
        for (int i = tid; i < KEEP; i += 256) g_idx[b * KEEP + i] = ix[i];
        return;
    }
    const int RT = QKV_RT;
    int row0 = blockIdx.x * RT;
    int bq = row0 / T_SEQ, t0 = row0 % T_SEQ;
    if (pass == 0) {
        float* cqs = (float*)smbuf;  // RT x 96
        for (int i = tid; i < RT * 96; i += 256) cqs[i] = g_cq[(size_t)(row0 + i / 96) * 96 + (i % 96)];
        __syncthreads();
        {
            int o0 = tid, o1 = tid + 256;
            float acc0[RT], acc1[RT];
            #pragma unroll
            for (int r = 0; r < RT; ++r) { acc0[r] = 0.f; acc1[r] = 0.f; }
            for (int c = 0; c < 96; c += 4) {
                float a0 = Wqn[c * 512 + o0], a1 = Wqn[(c + 1) * 512 + o0];
                float a2 = Wqn[(c + 2) * 512 + o0], a3 = Wqn[(c + 3) * 512 + o0];
                float b0 = Wqn[c * 512 + o1], b1 = Wqn[(c + 1) * 512 + o1];
                float b2 = Wqn[(c + 2) * 512 + o1], b3 = Wqn[(c + 3) * 512 + o1];
                #pragma unroll
                for (int r = 0; r < RT; ++r) {
                    float4 q = *(const float4*)&cqs[r * 96 + c];
                    acc0[r] += q.x * a0 + q.y * a1 + q.z * a2 + q.w * a3;
                    acc1[r] += q.x * b0 + q.y * b1 + q.z * b2 + q.w * b3;
                }
            }
            #pragma unroll
            for (int r = 0; r < RT; ++r) {
                size_t base = (size_t)bq * H_NUM * T_SEQ * HD + (size_t)(t0 + r) * HD;
                g_q[base + (size_t)(o0 >> 5) * T_SEQ * HD + (o0 & 31)] = acc0[r];
                g_q[base + (size_t)(o1 >> 5) * T_SEQ * HD + (o1 & 31)] = acc1[r];
            }
        }
        for (int p = tid; p < 512; p += 256) {
            int h = p >> 5, i = p & 31;
            float ar[RT], ai[RT];
            #pragma unroll
            for (int r = 0; r < RT; ++r) { ar[r] = 0.f; ai[r] = 0.f; }
            for (int c = 0; c < 96; c += 2) {
                float wr0 = Wqr[c * 1024 + h * 64 + i];
                float wi0 = Wqr[c * 1024 + h * 64 + 32 + i];
                float wr1 = Wqr[(c + 1) * 1024 + h * 64 + i];
                float wi1 = Wqr[(c + 1) * 1024 + h * 64 + 32 + i];
                #pragma unroll
                for (int r = 0; r < RT; ++r) {
                    float2 q = *(const float2*)&cqs[r * 96 + c];
                    ar[r] += q.x * wr0 + q.y * wr1;
                    ai[r] += q.x * wi0 + q.y * wi1;
                }
            }
            #pragma unroll
            for (int r = 0; r < RT; ++r) {
                int t = t0 + r;
                float co = g_costab[t * 32 + i], si = g_sintab[t * 32 + i];
                size_t base = ((size_t)(bq * H_NUM + h) * T_SEQ + t) * HD;
                g_q[base + 32 + i] = ar[r] * co - ai[r] * si;
                g_q[base + 64 + i] = ar[r] * si + ai[r] * co;
            }
        }
        return;
    }
    float* ckvs = (float*)smbuf;              // RT x 32
    float* krs  = ckvs + RT * 32;             // RT x 64
    for (int i = tid; i < RT * 32; i += 256) ckvs[i] = g_ckv[(size_t)(row0 + i / 32) * 32 + (i % 32)];
    for (int i = tid; i < RT * 64; i += 256) krs[i] = g_kr[(size_t)(row0 + i / 64) * 64 + (i % 64)];
    __syncthreads();
    for (int o = tid; o < 512; o += 256) {
        int h = o >> 5, d = o & 31;
        float acc[RT], accv[RT];
        #pragma unroll
        for (int r = 0; r < RT; ++r) { acc[r] = 0.f; accv[r] = 0.f; }
        for (int c = 0; c < 32; c += 4) {
            float k0 = Wkn[c * 512 + o], k1 = Wkn[(c + 1) * 512 + o];
            float k2 = Wkn[(c + 2) * 512 + o], k3 = Wkn[(c + 3) * 512 + o];
            float v0 = Wv[c * 512 + o], v1 = Wv[(c + 1) * 512 + o];
            float v2 = Wv[(c + 2) * 512 + o], v3 = Wv[(c + 3) * 512 + o];
            #pragma unroll
            for (int r = 0; r < RT; ++r) {
                float4 q = *(const float4*)&ckvs[r * 32 + c];
                acc[r]  += q.x * k0 + q.y * k1 + q.z * k2 + q.w * k3;
                accv[r] += q.x * v0 + q.y * v1 + q.z * v2 + q.w * v3;
            }
        }
        #pragma unroll
        for (int r = 0; r < RT; ++r) {
            size_t o2 = ((size_t)(bq * H_NUM + h) * T_SEQ + t0 + r) * HD + d;
            split_store(acc[r], &g_k1hi[o2], &g_k1lo[o2]);
        }
        #pragma unroll
        for (int r = 0; r < RT; r += 2) {
            __half2 hp = __floats2half2_rn(accv[r], accv[r + 1]);
            g_v1p[((size_t)(bq * H_NUM + h) * (T_SEQ / 2) + (t0 + r) / 2) * VD + d] = *(uint32_t*)&hp;
        }
    }
    for (int i = tid; i < RT * H_NUM * 64; i += 256) {
        int r = i / (H_NUM * 64); int rem = i % (H_NUM * 64); int h = rem / 64; int d = rem % 64;
        size_t o2 = ((size_t)(bq * H_NUM + h) * T_SEQ + t0 + r) * HD + 32 + d;
        split_store(krs[r * 64 + d], &g_k1hi[o2], &g_k1lo[o2]);
    }
}

// ---------------- tensor-core sel+window K,V projection ----------------
#define XROW_B 144
#define WROW_B 208
template <bool ISV>
__global__ void __launch_bounds__(128) kvproj_tc(int nwin) {
    __shared__ __align__(16) __nv_bfloat16 sxh[64 * 72], sxl[64 * 72];
    __shared__ __align__(16) __nv_bfloat16 swh[64 * 104], swl[64 * 104];
    __shared__ int sidx[64];
    const int NTN = ISV ? 8 : 12;
    int tid = threadIdx.x, lane = tid & 31, wr = tid >> 5;
    int g = lane >> 2, tg = lane & 3;
    bool sel = (int)blockIdx.x >= nwin;
    int rb = sel ? (blockIdx.x - nwin) : blockIdx.x;
    const int Tk = sel ? KEEP : T_SEQ;
    int row0 = rb * 64;
    int bq = row0 / Tk, s0 = row0 % Tk;
    int wn0 = blockIdx.y * (ISV ? 64 : 96);
    const int WN = ISV ? 512 : 1536;
    const __nv_bfloat16* Wh = ISV ? (sel ? g_wsv_h : g_wwv_h) : (sel ? g_wsk_h : g_wwk_h);
    const __nv_bfloat16* Wl = ISV ? (sel ? g_wsv_l : g_wwv_l) : (sel ? g_wsk_l : g_wwk_l);

    if (tid < 64) sidx[tid] = sel ? g_idx[bq * KEEP + s0 + tid] : (s0 + tid);
    __syncthreads();

    uint32_t sxh_u = (uint32_t)__cvta_generic_to_shared(sxh);
    uint32_t sxl_u = (uint32_t)__cvta_generic_to_shared(sxl);
    uint32_t swh_u = (uint32_t)__cvta_generic_to_shared(swh);
    uint32_t swl_u = (uint32_t)__cvta_generic_to_shared(swl);

    float acc[12][4];
    #pragma unroll
    for (int nt = 0; nt < 12; ++nt)
        #pragma unroll
        for (int e = 0; e < 4; ++e) acc[nt][e] = 0.f;

    const int nch = NTN;
    for (int kc = 0; kc < 4; ++kc) {
        for (int i = tid; i < 512; i += 128) {
            int r = i >> 3, c = i & 7;
            size_t src = (size_t)(bq * T_SEQ + sidx[r]) * C_DIM + kc * 64 + c * 8;
            cp16(sxh_u + r * XROW_B + c * 16, g_xh + src);
            cp16(sxl_u + r * XROW_B + c * 16, g_xl + src);
        }
        for (int i = tid; i < 64 * nch; i += 128) {
            int r = i / nch, c = i % nch;
            size_t src = (size_t)(kc * 64 + r) * WN + wn0 + c * 8;
            cp16(swh_u + r * WROW_B + c * 16, Wh + src);
            cp16(swl_u + r * WROW_B + c * 16, Wl + src);
        }
        asm volatile("cp.async.commit_group;");
        asm volatile("cp.async.wait_group 0;");
        __syncthreads();
        #pragma unroll
        for (int kt = 0; kt < 4; ++kt) {
            uint32_t aH[4], aL[4];
            uint32_t addrA = sxh_u + (wr * 16 + (lane & 15)) * XROW_B + (lane >> 4) * 16 + kt * 32;
            ldsm4(aH[0], aH[1], aH[2], aH[3], addrA);
            ldsm4(aL[0], aL[1], aL[2], aL[3], addrA + (sxl_u - sxh_u));
            uint32_t addrB0 = swh_u + (kt * 16 + (lane & 15)) * WROW_B + (lane >> 4) * 16;
            #pragma unroll
            for (int p = 0; p < NTN / 2; ++p) {
                uint32_t bh0, bh1, bh2, bh3, bl0, bl1, bl2, bl3;
                ldsm4t(bh0, bh1, bh2, bh3, addrB0 + p * 32);
                ldsm4t(bl0, bl1, bl2, bl3, addrB0 + p * 32 + (swl_u - swh_u));
                mma16bf(acc[2 * p],     aH, bh0, bh1);
                mma16bf(acc[2 * p],     aH, bl0, bl1);
                mma16bf(acc[2 * p],     aL, bh0, bh1);
                mma16bf(acc[2 * p + 1], aH, bh2, bh3);
                mma16bf(acc[2 * p + 1], aH, bl2, bl3);
                mma16bf(acc[2 * p + 1], aL, bh2, bh3);
            }
        }
        __syncthreads();
    }

    if (!ISV) {
        __nv_bfloat16* Khi = sel ? g_kshi : g_kwhi;
        __nv_bfloat16* Klo = sel ? g_kslo : g_kwlo;
        int h = blockIdx.y;
        #pragma unroll
        for (int nt = 0; nt < 4; ++nt) {
            #pragma unroll
            for (int e = 0; e < 4; ++e) {
                int d = nt * 8 + 2 * tg + (e & 1);
                int s = s0 + wr * 16 + g + ((e & 2) ? 8 : 0);
                size_t o2 = ((size_t)(bq * H_NUM + h) * Tk + s) * HD + d;
                split_store(acc[nt][e], &Khi[o2], &Klo[o2]);
            }
        }
        #pragma unroll
        for (int nt = 4; nt < 8; ++nt) {
            #pragma unroll
            for (int e = 0; e < 4; ++e) {
                int i = (nt - 4) * 8 + 2 * tg + (e & 1);
                int s = s0 + wr * 16 + g + ((e & 2) ? 8 : 0);
                float ar = acc[nt][e], ai = acc[nt + 4][e];
                float co = g_costab[s * 32 + i], si = g_sintab[s * 32 + i];
                size_t base = ((size_t)(bq * H_NUM + h) * Tk + s) * HD;
                split_store(ar * co - ai * si, &Khi[base + 32 + i], &Klo[base + 32 + i]);
                split_store(ar * si + ai * co, &Khi[base + 64 + i], &Klo[base + 64 + i]);
            }
        }
    } else {
        uint32_t* Vp = sel ? g_vsp : g_vwp;
        #pragma unroll
        for (int nt = 0; nt < 8; ++nt) {
            #pragma unroll
            for (int e = 0; e < 4; ++e) {
                float v0 = acc[nt][e];
                float v1 = __shfl_down_sync(0xffffffffu, v0, 4);
                if (!(g & 1)) {
                    int gc = wn0 + nt * 8 + 2 * tg + (e & 1);
                    int h = gc >> 5, d = gc & 31;
                    int s = s0 + wr * 16 + g + ((e & 2) ? 8 : 0);
                    __half2 hp = __floats2half2_rn(v0, v1);
                    Vp[((size_t)(bq * H_NUM + h) * (Tk / 2) + (s >> 1)) * VD + d] = *(uint32_t*)&hp;
                }
            }
        }
    }
}

// ---------------- fused flash attention (single-buffered: higher occupancy) ----------------
#define AQB 64
#define AKB 64
#define KROW_B   208
#define KBUF_B   (AKB * KROW_B)
#define LDVP 44
#define VBUF_B   (32 * LDVP * 4)
#define BUF_STRIDE (2 * KBUF_B + VBUF_B)
#define FA_SMEM BUF_STRIDE

__global__ void __launch_bounds__(128) attn_all() {
    extern __shared__ char smc[];
    uint32_t smem_u = (uint32_t)__cvta_generic_to_shared(smc);

    int mode = blockIdx.x >> 5;
    int qt = blockIdx.x & 31;
    if (mode == 0) qt = 31 - qt;
    int qt0 = qt * AQB;
    const int Tk = (mode == 1) ? KEEP : T_SEQ;
    int b = blockIdx.z, h = blockIdx.y;
    int tid = threadIdx.x;
    int w = tid >> 5, lane = tid & 31;
    int g = lane >> 2, tg = lane & 3;
    int r0 = w * 16;

    const __nv_bfloat16* KHI = (mode == 1) ? g_kshi : (mode == 2) ? g_kwhi : g_k1hi;
    const __nv_bfloat16* KLO = (mode == 1) ? g_kslo : (mode == 2) ? g_kwlo : g_k1lo;
    const uint32_t* VP = (mode == 1) ? g_vsp : (mode == 2) ? g_vwp : g_v1p;
    float* Oout = (mode == 1) ? g_O1 : (mode == 2) ? g_O2 : g_O0;
    const __nv_bfloat16* KbaseH = KHI + (size_t)(b * H_NUM + h) * Tk * HD;
    const __nv_bfloat16* KbaseL = KLO + (size_t)(b * H_NUM + h) * Tk * HD;
    const uint32_t* VPbase = VP + (size_t)(b * H_NUM + h) * (Tk / 2) * VD;
    const float* Qbase = g_q + ((size_t)(b * H_NUM + h) * T_SEQ + qt0) * HD;
    const float qscale = 0.14724444f; // log2(e)/sqrt(96)

    uint32_t lmoff = (uint32_t)(lane & 7) * KROW_B + (uint32_t)(lane >> 3) * 16;

    for (int i = tid; i < 32 * 8; i += 128) {
        int pr = i >> 3, c = 32 + (i & 7);
        ((uint32_t*)(smc + 2 * KBUF_B))[pr * LDVP + c] = (c == 32) ? 0x3C003C00u : 0u;
    }
    __syncthreads();

    uint32_t qhi[6][4], qlo[6][4];
    #pragma unroll
    for (int kc = 0; kc < 6; ++kc) {
        #pragma unroll
        for (int e = 0; e < 4; ++e) {
            int row = r0 + g + (e & 1) * 8;
            int col = kc * 16 + 2 * tg + (e & 2) * 4;
            float2 qv = *(const float2*)(Qbase + (size_t)row * HD + col);
            qv.x *= qscale; qv.y *= qscale;
            __nv_bfloat16 hx = __float2bfloat16(qv.x);
            __nv_bfloat16 hy = __float2bfloat16(qv.y);
            qhi[kc][e] = ((uint32_t)__bfloat16_as_ushort(hy) << 16) | __bfloat16_as_ushort(hx);
            __nv_bfloat16 lx = __float2bfloat16(qv.x - __bfloat162float(hx));
            __nv_bfloat16 ly = __float2bfloat16(qv.y - __bfloat162float(hy));
            qlo[kc][e] = ((uint32_t)__bfloat16_as_ushort(ly) << 16) | __bfloat16_as_ushort(lx);
        }
    }

    float oacc[5][4];
    #pragma unroll
    for (int nt = 0; nt < 5; ++nt)
        #pragma unroll
        for (int e = 0; e < 4; ++e) oacc[nt][e] = 0.f;

    int kend = (mode == 1) ? KEEP : (qt0 + AQB);
    int k0 = 0;
    if (mode == 2) { int a0 = qt0 - (WIN - 1); k0 = (a0 > 0) ? (a0 & ~(AKB - 1)) : 0; }

    for (int kt = k0; kt < kend; kt += AKB) {
        // stage tile (single buffer)
        {
            const uint4* sH = (const uint4*)(KbaseH + (size_t)kt * HD);
            const uint4* sL = (const uint4*)(KbaseL + (size_t)kt * HD);
            #pragma unroll
            for (int it = 0; it < 6; ++it) {
                int i = tid + it * 128;
                int r = i / 12, c = i % 12;
                cp16(smem_u + r * KROW_B + c * 16, sH + i);
                cp16(smem_u + KBUF_B + r * KROW_B + c * 16, sL + i);
            }
            const uint4* sV = (const uint4*)(VPbase + (size_t)(kt / 2) * VD);
            #pragma unroll
            for (int it = 0; it < 2; ++it) {
                int pc = tid + it * 128;
                cp16(smem_u + 2 * KBUF_B + (pc >> 3) * (LDVP * 4) + (pc & 7) * 16, sV + pc);
            }
            asm volatile("cp.async.commit_group;");
            asm volatile("cp.async.wait_group 0;");
        }
        __syncthreads();

        uint32_t baseH = smem_u + lmoff;
        uint32_t baseL = baseH + KBUF_B;
        const uint32_t* Vpb = (const uint32_t*)(smc + 2 * KBUF_B);

        float sacc[8][4];
        #pragma unroll
        for (int nt = 0; nt < 8; ++nt)
            #pragma unroll
            for (int e = 0; e < 4; ++e) sacc[nt][e] = 0.f;
        #pragma unroll
        for (int nt = 0; nt < 8; ++nt) {
            uint32_t aH = baseH + (uint32_t)nt * (8 * KROW_B);
            uint32_t aL = baseL + (uint32_t)nt * (8 * KROW_B);
            #pragma unroll
            for (int kp = 0; kp < 3; ++kp) {
                uint32_t h0, h1, h2, h3, l0, l1, l2, l3;
                ldsm4(h0, h1, h2, h3, aH + kp * 64);
                ldsm4(l0, l1, l2, l3, aL + kp * 64);
                int kc = 2 * kp;
                mma16bf(sacc[nt], qhi[kc], h0, h1);
                mma16bf(sacc[nt], qhi[kc], l0, l1);
                mma16bf(sacc[nt], qlo[kc], h0, h1);
                mma16bf(sacc[nt], qhi[kc + 1], h2, h3);
                mma16bf(sacc[nt], qhi[kc + 1], l2, l3);
                mma16bf(sacc[nt], qlo[kc + 1], h2, h3);
            }
        }

        bool need_mask = (mode == 2) || (mode == 0 && kt + AKB > qt0);
        if (need_mask) {
            #pragma unroll
            for (int nt = 0; nt < 8; ++nt) {
                #pragma unroll
                for (int e = 0; e < 4; ++e) {
                    int key = kt + nt * 8 + 2 * tg + (e & 1);
                    int row = qt0 + r0 + g + ((e & 2) ? 8 : 0);
                    bool ok = key <= row;
                    if (mode == 2) ok = ok && (row - key < WIN);
                    if (!ok) sacc[nt][e] = -1e30f;
                }
            }
        }

        uint32_t ph2[8][2];
        #pragma unroll
        for (int nt = 0; nt < 8; ++nt) {
            __half2 e0 = h2exp2(__floats2half2_rn(sacc[nt][0], sacc[nt][1]));
            __half2 e1 = h2exp2(__floats2half2_rn(sacc[nt][2], sacc[nt][3]));
            ph2[nt][0] = *(uint32_t*)&e0;
            ph2[nt][1] = *(uint32_t*)&e1;
        }

        #pragma unroll
        for (int kc2 = 0; kc2 < 4; ++kc2) {
            uint32_t pa[4] = { ph2[2 * kc2][0], ph2[2 * kc2][1],
                               ph2[2 * kc2 + 1][0], ph2[2 * kc2 + 1][1] };
            #pragma unroll
            for (int nt2 = 0; nt2 < 5; ++nt2) {
                uint32_t b0 = Vpb[(kc2 * 8 + tg) * LDVP + nt2 * 8 + g];
                uint32_t b1 = Vpb[(kc2 * 8 + tg + 4) * LDVP + nt2 * 8 + g];
                mma16h(oacc[nt2], pa, b0, b1);
            }
        }
        __syncthreads();
    }

    float l0 = __shfl_sync(0xffffffffu, oacc[4][0], lane & 28);
    float l1 = __shfl_sync(0xffffffffu, oacc[4][2], lane & 28);
    float gte = g_gate[b * 3 + mode];
    float inv0 = gte / l0, inv1 = gte / l1;
    #pragma unroll
    for (int nt = 0; nt < 4; ++nt) {
        #pragma unroll
        for (int e = 0; e < 4; ++e) {
            int row = qt0 + r0 + g + ((e & 2) ? 8 : 0);
            int col = nt * 8 + 2 * tg + (e & 1);
            Oout[((size_t)(b * T_SEQ + row) * H_NUM + h) * VD + col] =
                oacc[nt][e] * ((e & 2) ? inv1 : inv0);
        }
    }
}

// ---------------- final projection (sums 3 branch buffers) ----------------
__global__ void proj_kernel(const float* __restrict__ Wproj, float* __restrict__ out) {
    const int RT = 16;
    int row0 = blockIdx.x * RT;
    int tid = threadIdx.x; // 256
    __shared__ float Os[RT][512];
    const float4* O0 = (const float4*)(g_O0 + ((size_t)row0 << 9));
    const float4* O1 = (const float4*)(g_O1 + ((size_t)row0 << 9));
    const float4* O2 = (const float4*)(g_O2 + ((size_t)row0 << 9));
    for (int i = tid; i < RT * 128; i += 256) {
        float4 a = O0[i], b = O1[i], c = O2[i];
        a.x += b.x + c.x; a.y += b.y + c.y; a.z += b.z + c.z; a.w += b.w + c.w;
        ((float4*)Os)[i] = a;
    }
    __syncthreads();
    float acc[RT];
    #pragma unroll
    for (int r = 0; r < RT; ++r) acc[r] = 0.f;
    for (int c = 0; c < 512; c += 4) {
        float w0 = Wproj[c * 256 + tid], w1 = Wproj[(c + 1) * 256 + tid];
        float w2 = Wproj[(c + 2) * 256 + tid], w3 = Wproj[(c + 3) * 256 + tid];
        #pragma unroll
        for (int r = 0; r < RT; ++r) {
            float4 o = *(const float4*)&Os[r][c];
            acc[r] += o.x * w0 + o.y * w1 + o.z * w2 + o.w * w3;
        }
    }
    #pragma unroll
    for (int r = 0; r < RT; ++r) out[(size_t)(row0 + r) * 256 + tid] = acc[r];
}

// ---------------- launch ----------------
extern "C" void kernel_launch(void* const* d_in, const int* in_sizes, int n_in,
                              void* d_out, int out_size) {
    const float* x     = (const float*)d_in[0];
    const float* Wcq   = (const float*)d_in[1];
    const float* qnw   = (const float*)d_in[2];
    const float* Wqn   = (const float*)d_in[3];
    const float* Wqr   = (const float*)d_in[4];
    const float* Wckv  = (const float*)d_in[5];
    const float* kvnw  = (const float*)d_in[6];
    const float* Wkn   = (const float*)d_in[7];
    const float* Wv    = (const float*)d_in[8];
    const float* Wkr   = (const float*)d_in[9];
    const float* Wimp  = (const float*)d_in[10];
    const float* Wselk = (const float*)d_in[11];
    const float* Wselv = (const float*)d_in[12];
    const float* Wwink = (const float*)d_in[13];
    const float* Wwinv = (const float*)d_in[14];
    const float* Wgate = (const float*)d_in[15];
    const float* Wproj = (const float*)d_in[16];
    float* out = (float*)d_out;
    int B = in_sizes[0] / (T_SEQ * C_DIM);
    if (B < 1) B = 1; if (B > BMAX) B = BMAX;

    cudaFuncSetAttribute(attn_all, cudaFuncAttributeMaxDynamicSharedMemorySize, FA_SMEM);

    prep_kernel<<<256 + B * 16, 256>>>(x, B);
    convert_kernel<<<dim3(512, 5), 256>>>(x, Wwink, Wselk, Wwinv, Wselv, B);
    row_feat_gate_kernel<<<B * T_SEQ + 1, 256>>>(x, Wcq, qnw, Wckv, kvnw, Wkr, Wimp, Wgate, B);
    int nqkv = B * T_SEQ / QKV_RT;
    dim3 qgrid(nqkv + B, 2);
    qkv_topk_kernel<<<qgrid, 256>>>(Wqn, Wqr, Wkn, Wv, nqkv);

    int nwin64 = B * T_SEQ / 64, nsel64 = B * KEEP / 64;
    kvproj_tc<false><<<dim3(nwin64 + nsel64, 16), 128>>>(nwin64);
    kvproj_tc<true ><<<dim3(nwin64 + nsel64, 8), 128>>>(nwin64);

    dim3 agrid(96, H_NUM, B);
    attn_all<<<agrid, 128, FA_SMEM>>>();

    proj_kernel<<<B * T_SEQ / 16, 256>>>(Wproj, out);
}

// round 17
// speedup vs baseline: 1.1818x; 1.1275x over previous
#include <cuda_runtime.h>
#include <cuda_bf16.h>
#include <cuda_fp16.h>
#include <math.h>
#include <stdint.h>

#define T_SEQ 2048
#define C_DIM 256
#define H_NUM 16
#define NOPE 32
#define ROPE 64
#define HD 96
#define VD 32
#define KEEP 512
#define WIN 128
#define BMAX 2
#define EPSF 1e-6f

// ---------------- device scratch ----------------
__device__ float g_costab[T_SEQ * 32];
__device__ float g_sintab[T_SEQ * 32];
__device__ float g_cq[BMAX * T_SEQ * 96];
__device__ __nv_bfloat16 g_cqh[BMAX * T_SEQ * 96];
__device__ __nv_bfloat16 g_cql[BMAX * T_SEQ * 96];
__device__ float g_ckv[BMAX * T_SEQ * 32];
__device__ float g_kr[BMAX * T_SEQ * 64];
__device__ float g_imp[BMAX * T_SEQ];
__device__ int   g_idx[BMAX * KEEP];
__device__ float g_xpart[BMAX * 16 * C_DIM];
__device__ float g_gate[BMAX * 3];
__device__ float g_q [BMAX * H_NUM * T_SEQ * HD];
__device__ __nv_bfloat16 g_k1hi[BMAX * H_NUM * T_SEQ * HD];
__device__ __nv_bfloat16 g_k1lo[BMAX * H_NUM * T_SEQ * HD];
__device__ __nv_bfloat16 g_kshi[BMAX * H_NUM * KEEP * HD];
__device__ __nv_bfloat16 g_kslo[BMAX * H_NUM * KEEP * HD];
__device__ __nv_bfloat16 g_kwhi[BMAX * H_NUM * T_SEQ * HD];
__device__ __nv_bfloat16 g_kwlo[BMAX * H_NUM * T_SEQ * HD];
// V stored packed as half2 (low = even row, high = odd row), pair-row major
__device__ uint32_t g_v1p[BMAX * H_NUM * (T_SEQ / 2) * VD];
__device__ uint32_t g_vsp[BMAX * H_NUM * (KEEP / 2) * VD];
__device__ uint32_t g_vwp[BMAX * H_NUM * (T_SEQ / 2) * VD];
__device__ float g_O0[BMAX * T_SEQ * H_NUM * VD];
__device__ float g_O1[BMAX * T_SEQ * H_NUM * VD];
__device__ float g_O2[BMAX * T_SEQ * H_NUM * VD];
// bf16 hi/lo copies for tensor-core projections
__device__ __nv_bfloat16 g_xh[BMAX * T_SEQ * C_DIM];
__device__ __nv_bfloat16 g_xl[BMAX * T_SEQ * C_DIM];
__device__ __nv_bfloat16 g_wwk_h[C_DIM * 1536], g_wwk_l[C_DIM * 1536];
__device__ __nv_bfloat16 g_wsk_h[C_DIM * 1536], g_wsk_l[C_DIM * 1536];
__device__ __nv_bfloat16 g_wwv_h[C_DIM * 512],  g_wwv_l[C_DIM * 512];
__device__ __nv_bfloat16 g_wsv_h[C_DIM * 512],  g_wsv_l[C_DIM * 512];
__device__ __nv_bfloat16 g_wq_h[96 * 1536],     g_wq_l[96 * 1536];

__device__ __forceinline__ void mma16bf(float* c, const uint32_t* a, uint32_t b0, uint32_t b1) {
    asm volatile("mma.sync.aligned.m16n8k16.row.col.f32.bf16.bf16.f32 "
        "{%0,%1,%2,%3}, {%4,%5,%6,%7}, {%8,%9}, {%0,%1,%2,%3};"
        : "+f"(c[0]), "+f"(c[1]), "+f"(c[2]), "+f"(c[3])
        : "r"(a[0]), "r"(a[1]), "r"(a[2]), "r"(a[3]), "r"(b0), "r"(b1));
}
__device__ __forceinline__ void mma16h(float* c, const uint32_t* a, uint32_t b0, uint32_t b1) {
    asm volatile("mma.sync.aligned.m16n8k16.row.col.f32.f16.f16.f32 "
        "{%0,%1,%2,%3}, {%4,%5,%6,%7}, {%8,%9}, {%0,%1,%2,%3};"
        : "+f"(c[0]), "+f"(c[1]), "+f"(c[2]), "+f"(c[3])
        : "r"(a[0]), "r"(a[1]), "r"(a[2]), "r"(a[3]), "r"(b0), "r"(b1));
}
__device__ __forceinline__ void ldsm4(uint32_t& r0, uint32_t& r1, uint32_t& r2, uint32_t& r3,
                                      uint32_t addr) {
    asm volatile("ldmatrix.sync.aligned.m8n8.x4.shared.b16 {%0,%1,%2,%3}, [%4];"
        : "=r"(r0), "=r"(r1), "=r"(r2), "=r"(r3) : "r"(addr));
}
__device__ __forceinline__ void ldsm4t(uint32_t& r0, uint32_t& r1, uint32_t& r2, uint32_t& r3,
                                       uint32_t addr) {
    asm volatile("ldmatrix.sync.aligned.m8n8.x4.trans.shared.b16 {%0,%1,%2,%3}, [%4];"
        : "=r"(r0), "=r"(r1), "=r"(r2), "=r"(r3) : "r"(addr));
}
__device__ __forceinline__ void cp16(uint32_t dst, const void* src) {
    asm volatile("cp.async.cg.shared.global [%0], [%1], 16;" :: "r"(dst), "l"(src));
}
__device__ __forceinline__ void split_store(float v, __nv_bfloat16* hi, __nv_bfloat16* lo) {
    __nv_bfloat16 h = __float2bfloat16(v);
    *hi = h;
    *lo = __float2bfloat16(v - __bfloat162float(h));
}
// exclusive block scan over 256 threads (uses 8-int smem buffer)
__device__ __forceinline__ int blk_excl_scan256(int v, int tid, int* wsums) {
    __syncthreads();
    int lane = tid & 31, w = tid >> 5;
    int x = v;
    #pragma unroll
    for (int o = 1; o < 32; o <<= 1) {
        int y = __shfl_up_sync(0xffffffffu, x, o);
        if (lane >= o) x += y;
    }
    if (lane == 31) wsums[w] = x;
    __syncthreads();
    if (tid == 0) {
        int s = 0;
        #pragma unroll
        for (int i = 0; i < 8; ++i) { int t = wsums[i]; wsums[i] = s; s += t; }
    }
    __syncthreads();
    return wsums[w] + x - v;
}

// ---------------- prep: rope table + colmean partials ----------------
__global__ void prep_kernel(const float* __restrict__ x, int B) {
    if ((int)blockIdx.x < 256) {
        int id = blockIdx.x * 256 + threadIdx.x;
        int t = id >> 5, i = id & 31;
        float f = (float)pow(10000.0, -(double)i / 32.0);
        float ang = (float)t * f;
        g_costab[id] = cosf(ang);
        g_sintab[id] = sinf(ang);
    } else {
        int blk = blockIdx.x - 256;
        int b = blk >> 4, chunk = blk & 15;
        int c = threadIdx.x;
        const float* xp = x + ((size_t)b * T_SEQ + chunk * 128) * C_DIM + c;
        float s = 0.f;
        #pragma unroll 4
        for (int t = 0; t < 128; ++t) s += xp[(size_t)t * C_DIM];
        g_xpart[blk * C_DIM + c] = s;
    }
}

// ---------------- bf16 hi/lo conversion of x, sel/win weights, combined Wq ----------------
__global__ void convert_kernel(const float* __restrict__ x,
                               const float* __restrict__ wwk, const float* __restrict__ wsk,
                               const float* __restrict__ wwv, const float* __restrict__ wsv,
                               const float* __restrict__ wqn, const float* __restrict__ wqr,
                               int B) {
    int seg = blockIdx.y;
    if (seg == 5) {
        for (int i = blockIdx.x * 256 + threadIdx.x; i < 96 * 1536; i += 512 * 256) {
            int c = i / 1536, col = i % 1536;
            int h = col / 96, d = col % 96;
            float v = (d < 32) ? wqn[c * 512 + h * 32 + d] : wqr[c * 1024 + h * 64 + (d - 32)];
            split_store(v, &g_wq_h[i], &g_wq_l[i]);
        }
        return;
    }
    const float* src; __nv_bfloat16 *dh, *dl; int n;
    switch (seg) {
        case 0: src = x;   dh = g_xh;    dl = g_xl;    n = B * T_SEQ * C_DIM; break;
        case 1: src = wwk; dh = g_wwk_h; dl = g_wwk_l; n = C_DIM * 1536; break;
        case 2: src = wsk; dh = g_wsk_h; dl = g_wsk_l; n = C_DIM * 1536; break;
        case 3: src = wwv; dh = g_wwv_h; dl = g_wwv_l; n = C_DIM * 512;  break;
        default: src = wsv; dh = g_wsv_h; dl = g_wsv_l; n = C_DIM * 512;  break;
    }
    for (int i = blockIdx.x * 256 + threadIdx.x; i < n; i += 512 * 256)
        split_store(src[i], &dh[i], &dl[i]);
}

// ---------------- row features + gate (gate = last block) ----------------
__global__ void row_feat_gate_kernel(const float* __restrict__ x,
                                const float* __restrict__ Wcq, const float* __restrict__ qnw,
                                const float* __restrict__ Wckv, const float* __restrict__ kvnw,
                                const float* __restrict__ Wkr, const float* __restrict__ Wimp,
                                const float* __restrict__ Wgate, int B) {
    int tid = threadIdx.x; // 256
    int lane = tid & 31, w = tid >> 5;
    if ((int)blockIdx.x == B * T_SEQ) {
        __shared__ float lg[6];
        if (w < B * 3) {
            int b = w / 3, j = w % 3;
            float s = 0.f;
            for (int c = lane; c < C_DIM; c += 32) {
                float m = 0.f;
                #pragma unroll
                for (int p = 0; p < 16; ++p) m += g_xpart[(b * 16 + p) * C_DIM + c];
                s += (m / (float)T_SEQ) * Wgate[c * 3 + j];
            }
            #pragma unroll
            for (int o = 16; o > 0; o >>= 1) s += __shfl_xor_sync(0xffffffffu, s, o);
            if (lane == 0) lg[w] = s;
        }
        __syncthreads();
        if (tid < B) {
            float a = lg[tid * 3], b2 = lg[tid * 3 + 1], c2 = lg[tid * 3 + 2];
            float mx = fmaxf(a, fmaxf(b2, c2));
            float ea = expf(a - mx), eb = expf(b2 - mx), ec = expf(c2 - mx);
            float s = ea + eb + ec;
            g_gate[tid * 3 + 0] = ea / s;
            g_gate[tid * 3 + 1] = eb / s;
            g_gate[tid * 3 + 2] = ec / s;
        }
        return;
    }
    int row = blockIdx.x;
    int t = row % T_SEQ;
    __shared__ float xs[C_DIM];
    __shared__ float krbuf[64];
    __shared__ float red[4];
    xs[tid] = x[(size_t)row * C_DIM + tid];
    __syncthreads();
    float a = 0.f;
    if (tid < 96) {
        for (int c = 0; c < C_DIM; c += 4) {
            float4 xv = *(const float4*)&xs[c];
            a += xv.x * Wcq[c * 96 + tid] + xv.y * Wcq[(c + 1) * 96 + tid]
               + xv.z * Wcq[(c + 2) * 96 + tid] + xv.w * Wcq[(c + 3) * 96 + tid];
        }
    } else if (tid < 128) {
        int j = tid - 96;
        for (int c = 0; c < C_DIM; c += 4) {
            float4 xv = *(const float4*)&xs[c];
            a += xv.x * Wckv[c * 32 + j] + xv.y * Wckv[(c + 1) * 32 + j]
               + xv.z * Wckv[(c + 2) * 32 + j] + xv.w * Wckv[(c + 3) * 32 + j];
        }
    } else if (tid < 192) {
        int j = tid - 128;
        for (int c = 0; c < C_DIM; c += 4) {
            float4 xv = *(const float4*)&xs[c];
            a += xv.x * Wkr[c * 64 + j] + xv.y * Wkr[(c + 1) * 64 + j]
               + xv.z * Wkr[(c + 2) * 64 + j] + xv.w * Wkr[(c + 3) * 64 + j];
        }
        a *= (1.f / (float)H_NUM);
        krbuf[j] = a;
    } else if (tid == 192) {
        for (int c = 0; c < C_DIM; ++c) a += xs[c] * Wimp[c];
        g_imp[row] = a;
    }
    if (w < 4) {
        float sq = a * a;
        #pragma unroll
        for (int o = 16; o > 0; o >>= 1) sq += __shfl_xor_sync(0xffffffffu, sq, o);
        if (lane == 0) red[w] = sq;
    }
    __syncthreads();
    if (tid < 96) {
        float rms_cq = rsqrtf((red[0] + red[1] + red[2]) / 96.f + EPSF);
        float v = a * rms_cq * qnw[tid];
        g_cq[(size_t)row * 96 + tid] = v;
        split_store(v, &g_cqh[(size_t)row * 96 + tid], &g_cql[(size_t)row * 96 + tid]);
    } else if (tid < 128) {
        float rms_kv = rsqrtf(red[3] / 32.f + EPSF);
        g_ckv[(size_t)row * 32 + (tid - 96)] = a * rms_kv * kvnw[tid - 96];
    } else if (tid < 160) {
        int i = tid - 128;
        float xr = krbuf[i], xi = krbuf[32 + i];
        float co = g_costab[t * 32 + i], si = g_sintab[t * 32 + i];
        g_kr[(size_t)row * 64 + i]      = xr * co - xi * si;
        g_kr[(size_t)row * 64 + 32 + i] = xr * si + xi * co;
    }
}

// ---------------- tensor-core q projection (M=64, N=96 per head, K=96) ----------------
#define QX_B 80
#define QW_B 208
__global__ void __launch_bounds__(128) qproj_tc() {
    __shared__ __align__(16) __nv_bfloat16 sxh[64 * 40], sxl[64 * 40];
    __shared__ __align__(16) __nv_bfloat16 swh[32 * 104], swl[32 * 104];
    int tid = threadIdx.x, lane = tid & 31, wr = tid >> 5;
    int g = lane >> 2, tg = lane & 3;
    int row0 = blockIdx.x * 64;
    int bq = row0 / T_SEQ, t0 = row0 % T_SEQ;
    int h = blockIdx.y;
    int wn0 = h * 96;

    uint32_t sxh_u = (uint32_t)__cvta_generic_to_shared(sxh);
    uint32_t sxl_u = (uint32_t)__cvta_generic_to_shared(sxl);
    uint32_t swh_u = (uint32_t)__cvta_generic_to_shared(swh);
    uint32_t swl_u = (uint32_t)__cvta_generic_to_shared(swl);

    float acc[12][4];
    #pragma unroll
    for (int nt = 0; nt < 12; ++nt)
        #pragma unroll
        for (int e = 0; e < 4; ++e) acc[nt][e] = 0.f;

    for (int kc = 0; kc < 3; ++kc) {
        for (int i = tid; i < 256; i += 128) {
            int r = i >> 2, c = i & 3;
            size_t src = (size_t)(row0 + r) * 96 + kc * 32 + c * 8;
            cp16(sxh_u + r * QX_B + c * 16, g_cqh + src);
            cp16(sxl_u + r * QX_B + c * 16, g_cql + src);
        }
        for (int i = tid; i < 32 * 12; i += 128) {
            int r = i / 12, c = i % 12;
            size_t src = (size_t)(kc * 32 + r) * 1536 + wn0 + c * 8;
            cp16(swh_u + r * QW_B + c * 16, g_wq_h + src);
            cp16(swl_u + r * QW_B + c * 16, g_wq_l + src);
        }
        asm volatile("cp.async.commit_group;");
        asm volatile("cp.async.wait_group 0;");
        __syncthreads();
        #pragma unroll
        for (int kt = 0; kt < 2; ++kt) {
            uint32_t aH[4], aL[4];
            uint32_t addrA = sxh_u + (wr * 16 + (lane & 15)) * QX_B + (lane >> 4) * 16 + kt * 32;
            ldsm4(aH[0], aH[1], aH[2], aH[3], addrA);
            ldsm4(aL[0], aL[1], aL[2], aL[3], addrA + (sxl_u - sxh_u));
            uint32_t addrB0 = swh_u + (kt * 16 + (lane & 15)) * QW_B + (lane >> 4) * 16;
            #pragma unroll
            for (int p = 0; p < 6; ++p) {
                uint32_t bh0, bh1, bh2, bh3, bl0, bl1, bl2, bl3;
                ldsm4t(bh0, bh1, bh2, bh3, addrB0 + p * 32);
                ldsm4t(bl0, bl1, bl2, bl3, addrB0 + p * 32 + (swl_u - swh_u));
                mma16bf(acc[2 * p],     aH, bh0, bh1);
                mma16bf(acc[2 * p],     aH, bl0, bl1);
                mma16bf(acc[2 * p],     aL, bh0, bh1);
                mma16bf(acc[2 * p + 1], aH, bh2, bh3);
                mma16bf(acc[2 * p + 1], aH, bl2, bl3);
                mma16bf(acc[2 * p + 1], aL, bh2, bh3);
            }
        }
        __syncthreads();
    }

    #pragma unroll
    for (int nt = 0; nt < 4; ++nt) {
        #pragma unroll
        for (int e = 0; e < 4; ++e) {
            int d = nt * 8 + 2 * tg + (e & 1);
            int t = t0 + wr * 16 + g + ((e & 2) ? 8 : 0);
            g_q[((size_t)(bq * H_NUM + h) * T_SEQ + t) * HD + d] = acc[nt][e];
        }
    }
    #pragma unroll
    for (int nt = 4; nt < 8; ++nt) {
        #pragma unroll
        for (int e = 0; e < 4; ++e) {
            int i = (nt - 4) * 8 + 2 * tg + (e & 1);
            int t = t0 + wr * 16 + g + ((e & 2) ? 8 : 0);
            float ar = acc[nt][e], ai = acc[nt + 4][e];
            float co = g_costab[t * 32 + i], si = g_sintab[t * 32 + i];
            size_t base = ((size_t)(bq * H_NUM + h) * T_SEQ + t) * HD;
            g_q[base + 32 + i] = ar * co - ai * si;
            g_q[base + 64 + i] = ar * si + ai * co;
        }
    }
}

// ---------------- k/v scalar pass (K=32) + fast radix-select topk ----------------
#define QKV_RT 16
__global__ void qkv_topk_kernel(const float* __restrict__ Wkn, const float* __restrict__ Wv,
                                int nqkv) {
    __shared__ __align__(16) char smbuf[16640];
    int tid = threadIdx.x; // 256
    if ((int)blockIdx.x >= nqkv) {
        // ---- fast topk: radix select the 512th largest, then ordered compaction ----
        uint32_t* keys = (uint32_t*)smbuf;              // 8192 B
        int* hist = (int*)(smbuf + 8192);               // 1024 B
        int* wsums = (int*)(smbuf + 8192 + 1024);       // 32 B
        int* ctrl = (int*)(smbuf + 8192 + 1024 + 64);   // 2 ints
        int b = blockIdx.x - nqkv;
        for (int i = tid; i < T_SEQ; i += 256) {
            uint32_t bits = __float_as_uint(g_imp[b * T_SEQ + i]);
            keys[i] = bits ^ ((bits & 0x80000000u) ? 0xFFFFFFFFu : 0x80000000u);
        }
        __syncthreads();
        uint32_t prefix = 0; int k = KEEP;
        for (int shift = 24; shift >= 0; shift -= 8) {
            hist[tid] = 0;
            __syncthreads();
            for (int i = tid; i < T_SEQ; i += 256) {
                uint32_t u = keys[i];
                bool cand = (shift == 24) || (((u ^ prefix) >> (shift + 8)) == 0);
                if (cand) atomicAdd(&hist[(u >> shift) & 255], 1);
            }
            __syncthreads();
            if (tid == 0) {
                int acc = 0, bsel = 0;
                for (int bb = 255; bb >= 0; --bb) {
                    int hcnt = hist[bb];
                    if (acc + hcnt >= k) { bsel = bb; break; }
                    acc += hcnt;
                }
                ctrl[0] = (int)(prefix | ((uint32_t)bsel << shift));
                ctrl[1] = k - acc;
            }
            __syncthreads();
            prefix = (uint32_t)ctrl[0]; k = ctrl[1];
            __syncthreads();
        }
        uint32_t ustar = prefix;
        int m = k;  // number of ties (== ustar) to include, in ascending index order
        int base0 = tid * 8;
        int tie_cnt = 0;
        #pragma unroll
        for (int j = 0; j < 8; ++j) if (keys[base0 + j] == ustar) tie_cnt++;
        int tie_base = blk_excl_scan256(tie_cnt, tid, wsums);
        int sel_cnt = 0, trk = tie_base;
        #pragma unroll
        for (int j = 0; j < 8; ++j) {
            uint32_t u = keys[base0 + j];
            if (u > ustar) sel_cnt++;
            else if (u == ustar) { if (trk < m) sel_cnt++; trk++; }
        }
        int pos = blk_excl_scan256(sel_cnt, tid, wsums);
        trk = tie_base;
        #pragma unroll
        for (int j = 0; j < 8; ++j) {
            int i = base0 + j;
            uint32_t u = keys[i];
            bool s = false;
            if (u > ustar) s = true;
            else if (u == ustar) { if (trk < m) s = true; trk++; }
            if (s) g_idx[b * KEEP + pos++] = i;
        }
        return;
    }
    // ---- kv pass (K=32) ----
    const int RT = QKV_RT;
    int row0 = blockIdx.x * RT;
    int bq = row0 / T_SEQ, t0 = row0 % T_SEQ;
    float* ckvs = (float*)smbuf;              // RT x 32
    float* krs  = ckvs + RT * 32;             // RT x 64
    for (int i = tid; i < RT * 32; i += 256) ckvs[i] = g_ckv[(size_t)(row0 + i / 32) * 32 + (i % 32)];
    for (int i = tid; i < RT * 64; i += 256) krs[i] = g_kr[(size_t)(row0 + i / 64) * 64 + (i % 64)];
    __syncthreads();
    for (int o = tid; o < 512; o += 256) {
        int h = o >> 5, d = o & 31;
        float acc[RT], accv[RT];
        #pragma unroll
        for (int r = 0; r < RT; ++r) { acc[r] = 0.f; accv[r] = 0.f; }
        for (int c = 0; c < 32; c += 4) {
            float k0 = Wkn[c * 512 + o], k1 = Wkn[(c + 1) * 512 + o];
            float k2 = Wkn[(c + 2) * 512 + o], k3 = Wkn[(c + 3) * 512 + o];
            float v0 = Wv[c * 512 + o], v1 = Wv[(c + 1) * 512 + o];
            float v2 = Wv[(c + 2) * 512 + o], v3 = Wv[(c + 3) * 512 + o];
            #pragma unroll
            for (int r = 0; r < RT; ++r) {
                float4 q = *(const float4*)&ckvs[r * 32 + c];
                acc[r]  += q.x * k0 + q.y * k1 + q.z * k2 + q.w * k3;
                accv[r] += q.x * v0 + q.y * v1 + q.z * v2 + q.w * v3;
            }
        }
        #pragma unroll
        for (int r = 0; r < RT; ++r) {
            size_t o2 = ((size_t)(bq * H_NUM + h) * T_SEQ + t0 + r) * HD + d;
            split_store(acc[r], &g_k1hi[o2], &g_k1lo[o2]);
        }
        #pragma unroll
        for (int r = 0; r < RT; r += 2) {
            __half2 hp = __floats2half2_rn(accv[r], accv[r + 1]);
            g_v1p[((size_t)(bq * H_NUM + h) * (T_SEQ / 2) + (t0 + r) / 2) * VD + d] = *(uint32_t*)&hp;
        }
    }
    for (int i = tid; i < RT * H_NUM * 64; i += 256) {
        int r = i / (H_NUM * 64); int rem = i % (H_NUM * 64); int h = rem / 64; int d = rem % 64;
        size_t o2 = ((size_t)(bq * H_NUM + h) * T_SEQ + t0 + r) * HD + 32 + d;
        split_store(krs[r * 64 + d], &g_k1hi[o2], &g_k1lo[o2]);
    }
}

// ---------------- tensor-core sel+window K,V projection ----------------
#define XROW_B 144
#define WROW_B 208
template <bool ISV>
__global__ void __launch_bounds__(128) kvproj_tc(int nwin) {
    __shared__ __align__(16) __nv_bfloat16 sxh[64 * 72], sxl[64 * 72];
    __shared__ __align__(16) __nv_bfloat16 swh[64 * 104], swl[64 * 104];
    __shared__ int sidx[64];
    const int NTN = ISV ? 8 : 12;
    int tid = threadIdx.x, lane = tid & 31, wr = tid >> 5;
    int g = lane >> 2, tg = lane & 3;
    bool sel = (int)blockIdx.x >= nwin;
    int rb = sel ? (blockIdx.x - nwin) : blockIdx.x;
    const int Tk = sel ? KEEP : T_SEQ;
    int row0 = rb * 64;
    int bq = row0 / Tk, s0 = row0 % Tk;
    int wn0 = blockIdx.y * (ISV ? 64 : 96);
    const int WN = ISV ? 512 : 1536;
    const __nv_bfloat16* Wh = ISV ? (sel ? g_wsv_h : g_wwv_h) : (sel ? g_wsk_h : g_wwk_h);
    const __nv_bfloat16* Wl = ISV ? (sel ? g_wsv_l : g_wwv_l) : (sel ? g_wsk_l : g_wwk_l);

    if (tid < 64) sidx[tid] = sel ? g_idx[bq * KEEP + s0 + tid] : (s0 + tid);
    __syncthreads();

    uint32_t sxh_u = (uint32_t)__cvta_generic_to_shared(sxh);
    uint32_t sxl_u = (uint32_t)__cvta_generic_to_shared(sxl);
    uint32_t swh_u = (uint32_t)__cvta_generic_to_shared(swh);
    uint32_t swl_u = (uint32_t)__cvta_generic_to_shared(swl);

    float acc[12][4];
    #pragma unroll
    for (int nt = 0; nt < 12; ++nt)
        #pragma unroll
        for (int e = 0; e < 4; ++e) acc[nt][e] = 0.f;

    const int nch = NTN;
    for (int kc = 0; kc < 4; ++kc) {
        for (int i = tid; i < 512; i += 128) {
            int r = i >> 3, c = i & 7;
            size_t src = (size_t)(bq * T_SEQ + sidx[r]) * C_DIM + kc * 64 + c * 8;
            cp16(sxh_u + r * XROW_B + c * 16, g_xh + src);
            cp16(sxl_u + r * XROW_B + c * 16, g_xl + src);
        }
        for (int i = tid; i < 64 * nch; i += 128) {
            int r = i / nch, c = i % nch;
            size_t src = (size_t)(kc * 64 + r) * WN + wn0 + c * 8;
            cp16(swh_u + r * WROW_B + c * 16, Wh + src);
            cp16(swl_u + r * WROW_B + c * 16, Wl + src);
        }
        asm volatile("cp.async.commit_group;");
        asm volatile("cp.async.wait_group 0;");
        __syncthreads();
        #pragma unroll
        for (int kt = 0; kt < 4; ++kt) {
            uint32_t aH[4], aL[4];
            uint32_t addrA = sxh_u + (wr * 16 + (lane & 15)) * XROW_B + (lane >> 4) * 16 + kt * 32;
            ldsm4(aH[0], aH[1], aH[2], aH[3], addrA);
            ldsm4(aL[0], aL[1], aL[2], aL[3], addrA + (sxl_u - sxh_u));
            uint32_t addrB0 = swh_u + (kt * 16 + (lane & 15)) * WROW_B + (lane >> 4) * 16;
            #pragma unroll
            for (int p = 0; p < NTN / 2; ++p) {
                uint32_t bh0, bh1, bh2, bh3, bl0, bl1, bl2, bl3;
                ldsm4t(bh0, bh1, bh2, bh3, addrB0 + p * 32);
                ldsm4t(bl0, bl1, bl2, bl3, addrB0 + p * 32 + (swl_u - swh_u));
                mma16bf(acc[2 * p],     aH, bh0, bh1);
                mma16bf(acc[2 * p],     aH, bl0, bl1);
                mma16bf(acc[2 * p],     aL, bh0, bh1);
                mma16bf(acc[2 * p + 1], aH, bh2, bh3);
                mma16bf(acc[2 * p + 1], aH, bl2, bl3);
                mma16bf(acc[2 * p + 1], aL, bh2, bh3);
            }
        }
        __syncthreads();
    }

    if (!ISV) {
        __nv_bfloat16* Khi = sel ? g_kshi : g_kwhi;
        __nv_bfloat16* Klo = sel ? g_kslo : g_kwlo;
        int h = blockIdx.y;
        #pragma unroll
        for (int nt = 0; nt < 4; ++nt) {
            #pragma unroll
            for (int e = 0; e < 4; ++e) {
                int d = nt * 8 + 2 * tg + (e & 1);
                int s = s0 + wr * 16 + g + ((e & 2) ? 8 : 0);
                size_t o2 = ((size_t)(bq * H_NUM + h) * Tk + s) * HD + d;
                split_store(acc[nt][e], &Khi[o2], &Klo[o2]);
            }
        }
        #pragma unroll
        for (int nt = 4; nt < 8; ++nt) {
            #pragma unroll
            for (int e = 0; e < 4; ++e) {
                int i = (nt - 4) * 8 + 2 * tg + (e & 1);
                int s = s0 + wr * 16 + g + ((e & 2) ? 8 : 0);
                float ar = acc[nt][e], ai = acc[nt + 4][e];
                float co = g_costab[s * 32 + i], si = g_sintab[s * 32 + i];
                size_t base = ((size_t)(bq * H_NUM + h) * Tk + s) * HD;
                split_store(ar * co - ai * si, &Khi[base + 32 + i], &Klo[base + 32 + i]);
                split_store(ar * si + ai * co, &Khi[base + 64 + i], &Klo[base + 64 + i]);
            }
        }
    } else {
        uint32_t* Vp = sel ? g_vsp : g_vwp;
        #pragma unroll
        for (int nt = 0; nt < 8; ++nt) {
            #pragma unroll
            for (int e = 0; e < 4; ++e) {
                float v0 = acc[nt][e];
                float v1 = __shfl_down_sync(0xffffffffu, v0, 4);
                if (!(g & 1)) {
                    int gc = wn0 + nt * 8 + 2 * tg + (e & 1);
                    int h = gc >> 5, d = gc & 31;
                    int s = s0 + wr * 16 + g + ((e & 2) ? 8 : 0);
                    __half2 hp = __floats2half2_rn(v0, v1);
                    Vp[((size_t)(bq * H_NUM + h) * (Tk / 2) + (s >> 1)) * VD + d] = *(uint32_t*)&hp;
                }
            }
        }
    }
}

// ---------------- fused flash attention (cp.async double-buffered; R12 best) ----------------
#define AQB 64
#define AKB 64
#define KROW_B   208
#define KBUF_B   (AKB * KROW_B)
#define LDVP 44
#define VBUF_B   (32 * LDVP * 4)
#define BUF_STRIDE (2 * KBUF_B + VBUF_B)
#define FA_SMEM (2 * BUF_STRIDE)

__global__ void __launch_bounds__(128) attn_all() {
    extern __shared__ char smc[];
    uint32_t smem_u = (uint32_t)__cvta_generic_to_shared(smc);

    int mode = blockIdx.x >> 5;
    int qt = blockIdx.x & 31;
    if (mode == 0) qt = 31 - qt;
    int qt0 = qt * AQB;
    const int Tk = (mode == 1) ? KEEP : T_SEQ;
    int b = blockIdx.z, h = blockIdx.y;
    int tid = threadIdx.x;
    int w = tid >> 5, lane = tid & 31;
    int g = lane >> 2, tg = lane & 3;
    int r0 = w * 16;

    const __nv_bfloat16* KHI = (mode == 1) ? g_kshi : (mode == 2) ? g_kwhi : g_k1hi;
    const __nv_bfloat16* KLO = (mode == 1) ? g_kslo : (mode == 2) ? g_kwlo : g_k1lo;
    const uint32_t* VP = (mode == 1) ? g_vsp : (mode == 2) ? g_vwp : g_v1p;
    float* Oout = (mode == 1) ? g_O1 : (mode == 2) ? g_O2 : g_O0;
    const __nv_bfloat16* KbaseH = KHI + (size_t)(b * H_NUM + h) * Tk * HD;
    const __nv_bfloat16* KbaseL = KLO + (size_t)(b * H_NUM + h) * Tk * HD;
    const uint32_t* VPbase = VP + (size_t)(b * H_NUM + h) * (Tk / 2) * VD;
    const float* Qbase = g_q + ((size_t)(b * H_NUM + h) * T_SEQ + qt0) * HD;
    const float qscale = 0.14724444f; // log2(e)/sqrt(96)

    uint32_t lmoff = (uint32_t)(lane & 7) * KROW_B + (uint32_t)(lane >> 3) * 16;

    for (int i = tid; i < 2 * 32 * 8; i += 128) {
        int buf = i >> 8, rem = i & 255;
        int pr = rem >> 3, c = 32 + (rem & 7);
        ((uint32_t*)(smc + buf * BUF_STRIDE + 2 * KBUF_B))[pr * LDVP + c] =
            (c == 32) ? 0x3C003C00u : 0u;
    }
    __syncthreads();

    uint32_t qhi[6][4], qlo[6][4];
    #pragma unroll
    for (int kc = 0; kc < 6; ++kc) {
        #pragma unroll
        for (int e = 0; e < 4; ++e) {
            int row = r0 + g + (e & 1) * 8;
            int col = kc * 16 + 2 * tg + (e & 2) * 4;
            float2 qv = *(const float2*)(Qbase + (size_t)row * HD + col);
            qv.x *= qscale; qv.y *= qscale;
            __nv_bfloat16 hx = __float2bfloat16(qv.x);
            __nv_bfloat16 hy = __float2bfloat16(qv.y);
            qhi[kc][e] = ((uint32_t)__bfloat16_as_ushort(hy) << 16) | __bfloat16_as_ushort(hx);
            __nv_bfloat16 lx = __float2bfloat16(qv.x - __bfloat162float(hx));
            __nv_bfloat16 ly = __float2bfloat16(qv.y - __bfloat162float(hy));
            qlo[kc][e] = ((uint32_t)__bfloat16_as_ushort(ly) << 16) | __bfloat16_as_ushort(lx);
        }
    }

    float oacc[5][4];
    #pragma unroll
    for (int nt = 0; nt < 5; ++nt)
        #pragma unroll
        for (int e = 0; e < 4; ++e) oacc[nt][e] = 0.f;

    int kend = (mode == 1) ? KEEP : (qt0 + AQB);
    int k0 = 0;
    if (mode == 2) { int a0 = qt0 - (WIN - 1); k0 = (a0 > 0) ? (a0 & ~(AKB - 1)) : 0; }

    auto prefetch = [&](int kt, int buf) {
        uint32_t kd = smem_u + buf * BUF_STRIDE;
        const uint4* sH = (const uint4*)(KbaseH + (size_t)kt * HD);
        const uint4* sL = (const uint4*)(KbaseL + (size_t)kt * HD);
        #pragma unroll
        for (int it = 0; it < 6; ++it) {
            int i = tid + it * 128;
            int r = i / 12, c = i % 12;
            cp16(kd + r * KROW_B + c * 16, sH + i);
            cp16(kd + KBUF_B + r * KROW_B + c * 16, sL + i);
        }
        const uint4* sV = (const uint4*)(VPbase + (size_t)(kt / 2) * VD);
        #pragma unroll
        for (int it = 0; it < 2; ++it) {
            int pc = tid + it * 128;
            cp16(kd + 2 * KBUF_B + (pc >> 3) * (LDVP * 4) + (pc & 7) * 16, sV + pc);
        }
    };

    prefetch(k0, 0);
    asm volatile("cp.async.commit_group;");
    int buf = 0;

    for (int kt = k0; kt < kend; kt += AKB) {
        int nxt = kt + AKB;
        if (nxt < kend) {
            prefetch(nxt, buf ^ 1);
            asm volatile("cp.async.commit_group;");
            asm volatile("cp.async.wait_group 1;");
        } else {
            asm volatile("cp.async.wait_group 0;");
        }
        __syncthreads();

        uint32_t baseH = smem_u + buf * BUF_STRIDE + lmoff;
        uint32_t baseL = baseH + KBUF_B;
        const uint32_t* Vpb = (const uint32_t*)(smc + buf * BUF_STRIDE + 2 * KBUF_B);

        float sacc[8][4];
        #pragma unroll
        for (int nt = 0; nt < 8; ++nt)
            #pragma unroll
            for (int e = 0; e < 4; ++e) sacc[nt][e] = 0.f;
        #pragma unroll
        for (int nt = 0; nt < 8; ++nt) {
            uint32_t aH = baseH + (uint32_t)nt * (8 * KROW_B);
            uint32_t aL = baseL + (uint32_t)nt * (8 * KROW_B);
            #pragma unroll
            for (int kp = 0; kp < 3; ++kp) {
                uint32_t h0, h1, h2, h3, l0, l1, l2, l3;
                ldsm4(h0, h1, h2, h3, aH + kp * 64);
                ldsm4(l0, l1, l2, l3, aL + kp * 64);
                int kc = 2 * kp;
                mma16bf(sacc[nt], qhi[kc], h0, h1);
                mma16bf(sacc[nt], qhi[kc], l0, l1);
                mma16bf(sacc[nt], qlo[kc], h0, h1);
                mma16bf(sacc[nt], qhi[kc + 1], h2, h3);
                mma16bf(sacc[nt], qhi[kc + 1], l2, l3);
                mma16bf(sacc[nt], qlo[kc + 1], h2, h3);
            }
        }

        bool need_mask = (mode == 2) || (mode == 0 && kt + AKB > qt0);
        if (need_mask) {
            #pragma unroll
            for (int nt = 0; nt < 8; ++nt) {
                #pragma unroll
                for (int e = 0; e < 4; ++e) {
                    int key = kt + nt * 8 + 2 * tg + (e & 1);
                    int row = qt0 + r0 + g + ((e & 2) ? 8 : 0);
                    bool ok = key <= row;
                    if (mode == 2) ok = ok && (row - key < WIN);
                    if (!ok) sacc[nt][e] = -1e30f;
                }
            }
        }

        uint32_t ph2[8][2];
        #pragma unroll
        for (int nt = 0; nt < 8; ++nt) {
            __half2 e0 = h2exp2(__floats2half2_rn(sacc[nt][0], sacc[nt][1]));
            __half2 e1 = h2exp2(__floats2half2_rn(sacc[nt][2], sacc[nt][3]));
            ph2[nt][0] = *(uint32_t*)&e0;
            ph2[nt][1] = *(uint32_t*)&e1;
        }

        #pragma unroll
        for (int kc2 = 0; kc2 < 4; ++kc2) {
            uint32_t pa[4] = { ph2[2 * kc2][0], ph2[2 * kc2][1],
                               ph2[2 * kc2 + 1][0], ph2[2 * kc2 + 1][1] };
            #pragma unroll
            for (int nt2 = 0; nt2 < 5; ++nt2) {
                uint32_t b0 = Vpb[(kc2 * 8 + tg) * LDVP + nt2 * 8 + g];
                uint32_t b1 = Vpb[(kc2 * 8 + tg + 4) * LDVP + nt2 * 8 + g];
                mma16h(oacc[nt2], pa, b0, b1);
            }
        }
        __syncthreads();
        buf ^= 1;
    }

    float l0 = __shfl_sync(0xffffffffu, oacc[4][0], lane & 28);
    float l1 = __shfl_sync(0xffffffffu, oacc[4][2], lane & 28);
    float gte = g_gate[b * 3 + mode];
    float inv0 = gte / l0, inv1 = gte / l1;
    #pragma unroll
    for (int nt = 0; nt < 4; ++nt) {
        #pragma unroll
        for (int e = 0; e < 4; ++e) {
            int row = qt0 + r0 + g + ((e & 2) ? 8 : 0);
            int col = nt * 8 + 2 * tg + (e & 1);
            Oout[((size_t)(b * T_SEQ + row) * H_NUM + h) * VD + col] =
                oacc[nt][e] * ((e & 2) ? inv1 : inv0);
        }
    }
}

// ---------------- final projection (sums 3 branch buffers) ----------------
__global__ void proj_kernel(const float* __restrict__ Wproj, float* __restrict__ out) {
    const int RT = 16;
    int row0 = blockIdx.x * RT;
    int tid = threadIdx.x; // 256
    __shared__ float Os[RT][512];
    const float4* O0 = (const float4*)(g_O0 + ((size_t)row0 << 9));
    const float4* O1 = (const float4*)(g_O1 + ((size_t)row0 << 9));
    const float4* O2 = (const float4*)(g_O2 + ((size_t)row0 << 9));
    for (int i = tid; i < RT * 128; i += 256) {
        float4 a = O0[i], b = O1[i], c = O2[i];
        a.x += b.x + c.x; a.y += b.y + c.y; a.z += b.z + c.z; a.w += b.w + c.w;
        ((float4*)Os)[i] = a;
    }
    __syncthreads();
    float acc[RT];
    #pragma unroll
    for (int r = 0; r < RT; ++r) acc[r] = 0.f;
    for (int c = 0; c < 512; c += 4) {
        float w0 = Wproj[c * 256 + tid], w1 = Wproj[(c + 1) * 256 + tid];
        float w2 = Wproj[(c + 2) * 256 + tid], w3 = Wproj[(c + 3) * 256 + tid];
        #pragma unroll
        for (int r = 0; r < RT; ++r) {
            float4 o = *(const float4*)&Os[r][c];
            acc[r] += o.x * w0 + o.y * w1 + o.z * w2 + o.w * w3;
        }
    }
    #pragma unroll
    for (int r = 0; r < RT; ++r) out[(size_t)(row0 + r) * 256 + tid] = acc[r];
}

// ---------------- launch ----------------
extern "C" void kernel_launch(void* const* d_in, const int* in_sizes, int n_in,
                              void* d_out, int out_size) {
    const float* x     = (const float*)d_in[0];
    const float* Wcq   = (const float*)d_in[1];
    const float* qnw   = (const float*)d_in[2];
    const float* Wqn   = (const float*)d_in[3];
    const float* Wqr   = (const float*)d_in[4];
    const float* Wckv  = (const float*)d_in[5];
    const float* kvnw  = (const float*)d_in[6];
    const float* Wkn   = (const float*)d_in[7];
    const float* Wv    = (const float*)d_in[8];
    const float* Wkr   = (const float*)d_in[9];
    const float* Wimp  = (const float*)d_in[10];
    const float* Wselk = (const float*)d_in[11];
    const float* Wselv = (const float*)d_in[12];
    const float* Wwink = (const float*)d_in[13];
    const float* Wwinv = (const float*)d_in[14];
    const float* Wgate = (const float*)d_in[15];
    const float* Wproj = (const float*)d_in[16];
    float* out = (float*)d_out;
    int B = in_sizes[0] / (T_SEQ * C_DIM);
    if (B < 1) B = 1; if (B > BMAX) B = BMAX;

    cudaFuncSetAttribute(attn_all, cudaFuncAttributeMaxDynamicSharedMemorySize, FA_SMEM);

    prep_kernel<<<256 + B * 16, 256>>>(x, B);
    convert_kernel<<<dim3(512, 6), 256>>>(x, Wwink, Wselk, Wwinv, Wselv, Wqn, Wqr, B);
    row_feat_gate_kernel<<<B * T_SEQ + 1, 256>>>(x, Wcq, qnw, Wckv, kvnw, Wkr, Wimp, Wgate, B);

    qproj_tc<<<dim3(B * T_SEQ / 64, 16), 128>>>();
    int nqkv = B * T_SEQ / QKV_RT;
    qkv_topk_kernel<<<nqkv + B, 256>>>(Wkn, Wv, nqkv);

    int nwin64 = B * T_SEQ / 64, nsel64 = B * KEEP / 64;
    kvproj_tc<false><<<dim3(nwin64 + nsel64, 16), 128>>>(nwin64);
    kvproj_tc<true ><<<dim3(nwin64 + nsel64, 8), 128>>>(nwin64);

    dim3 agrid(96, H_NUM, B);
    attn_all<<<agrid, 128, FA_SMEM>>>();

    proj_kernel<<<B * T_SEQ / 16, 256>>>(Wproj, out);
}